// round 2
// baseline (speedup 1.0000x reference)
#include <cuda_runtime.h>
#include <cstdint>

// ---------------------------------------------------------------------------
// Fused gated-readout:
//   gate = sigmoid(MLP_g([h0;hT]))   512->128->256->128->256
//   val  = MLP_o(hT)                 256->128->256->128->256
//   out[b,:] = sum_n mask(b,n) * gate(b,n,:) * val(b,n,:)
// B=512, N=256, D=256, T=256.  131072 rows total.
// One CTA = 64 rows (all same b). All 8 layers fused via SMEM ping buffer +
// tf32 mma.sync.m16n8k8.  No intermediate global traffic.
// ---------------------------------------------------------------------------

#define THREADS 256
#define MTILE   64
#define BP      260                    // buf pitch (floats), 260 % 32 == 4 (A-frag friendly)
#define BUF_F   (MTILE * BP)           // 16640 floats
#define WBUF_F  34816                  // max K*(N+8) = 256*136
#define BIAS_F  1536
#define SMEM_F  (BUF_F + WBUF_F + BIAS_F + 64 + 256)   // 53312 floats
#define SMEM_BYTES (SMEM_F * 4)        // 213248 B  (< 227 KB dynamic max)

__device__ __forceinline__ float tf32r(float x) {
    uint32_t v;
    asm("cvt.rna.tf32.f32 %0, %1;" : "=r"(v) : "f"(x));
    return __uint_as_float(v);
}

__device__ __forceinline__ void mma8(float* d,
                                     uint32_t a0, uint32_t a1, uint32_t a2, uint32_t a3,
                                     uint32_t b0, uint32_t b1) {
    asm volatile(
        "mma.sync.aligned.m16n8k8.row.col.f32.tf32.tf32.f32 "
        "{%0,%1,%2,%3}, {%4,%5,%6,%7}, {%8,%9}, {%0,%1,%2,%3};"
        : "+f"(d[0]), "+f"(d[1]), "+f"(d[2]), "+f"(d[3])
        : "r"(a0), "r"(a1), "r"(a2), "r"(a3), "r"(b0), "r"(b1));
}

// Stage a [K,N] row-major fp32 weight into SMEM as tf32 with pitch N+8
// ((N+8)%32==8 -> B-fragment LDS is conflict-free for the 4row x 8col pattern).
template <int K, int N>
__device__ __forceinline__ void stage_w(float* __restrict__ wbuf,
                                        const float* __restrict__ W, int tid) {
    constexpr int WP = N + 8;
    constexpr int SH = (N == 128) ? 7 : 8;
    #pragma unroll 4
    for (int idx = tid; idx < K * N; idx += THREADS) {
        int k = idx >> SH;
        int n = idx & (N - 1);
        wbuf[k * WP + n] = tf32r(W[idx]);
    }
}

// GEMM layer: acc[16 x N/2 per warp] += buf[64,K] @ wbuf[K,N]
// warp grid: 4 M-groups x 2 N-groups; per-warp NT = (N/2)/8 n-tiles of m16n8k8.
template <int K, int N>
__device__ __forceinline__ void mma_layer(const float* __restrict__ buf,
                                          const float* __restrict__ wbuf,
                                          float* acc, int mrow, int nw, int g, int t) {
    constexpr int WP = N + 8;
    constexpr int NT = (N / 2) / 8;
    const int nbase = nw * (N / 2);
    #pragma unroll 4
    for (int k0 = 0; k0 < K; k0 += 8) {
        const float* r0 = buf + (mrow + g) * BP + k0 + t;
        const float* r8 = buf + (mrow + g + 8) * BP + k0 + t;
        uint32_t a0 = __float_as_uint(r0[0]);
        uint32_t a1 = __float_as_uint(r8[0]);
        uint32_t a2 = __float_as_uint(r0[4]);
        uint32_t a3 = __float_as_uint(r8[4]);
        const float* w0 = wbuf + (k0 + t) * WP + nbase + g;
        const float* w1 = wbuf + (k0 + t + 4) * WP + nbase + g;
        #pragma unroll
        for (int nt = 0; nt < NT; nt++) {
            uint32_t b0 = __float_as_uint(w0[nt * 8]);
            uint32_t b1 = __float_as_uint(w1[nt * 8]);
            mma8(acc + 4 * nt, a0, a1, a2, a3, b0, b1);
        }
    }
}

// Write acc (+bias, optional ReLU) back into buf as tf32-rounded activations.
template <int N, bool RELU>
__device__ __forceinline__ void store_act(float* __restrict__ buf,
                                          const float* __restrict__ acc,
                                          const float* __restrict__ bias,
                                          int mrow, int nw, int g, int t) {
    constexpr int NT = (N / 2) / 8;
    #pragma unroll
    for (int nt = 0; nt < NT; nt++) {
        int c = nw * (N / 2) + nt * 8 + 2 * t;
        float b0 = bias[c], b1 = bias[c + 1];
        float v0 = acc[4 * nt + 0] + b0;
        float v1 = acc[4 * nt + 1] + b1;
        float v2 = acc[4 * nt + 2] + b0;
        float v3 = acc[4 * nt + 3] + b1;
        if (RELU) {
            v0 = fmaxf(v0, 0.f); v1 = fmaxf(v1, 0.f);
            v2 = fmaxf(v2, 0.f); v3 = fmaxf(v3, 0.f);
        }
        buf[(mrow + g) * BP + c]         = tf32r(v0);
        buf[(mrow + g) * BP + c + 1]     = tf32r(v1);
        buf[(mrow + g + 8) * BP + c]     = tf32r(v2);
        buf[(mrow + g + 8) * BP + c + 1] = tf32r(v3);
    }
}

// Stage a [64,256] input tile (tf32-rounded) into buf; optionally accumulate
// fp32 row sums into mask_sh (for the validity mask).
__device__ __forceinline__ void stage_in(float* __restrict__ buf,
                                         const float* __restrict__ X,
                                         size_t row0, float* mask_sh, int tid) {
    const int col = tid;            // 256 threads == 256 cols
    const int lane = tid & 31;
    const float* src = X + row0 * 256 + col;
    #pragma unroll 4
    for (int r = 0; r < MTILE; r++) {
        float v = src[(size_t)r * 256];
        if (mask_sh) {
            float s = v;
            s += __shfl_xor_sync(0xffffffffu, s, 16);
            s += __shfl_xor_sync(0xffffffffu, s, 8);
            s += __shfl_xor_sync(0xffffffffu, s, 4);
            s += __shfl_xor_sync(0xffffffffu, s, 2);
            s += __shfl_xor_sync(0xffffffffu, s, 1);
            if (lane == 0) atomicAdd(&mask_sh[r], s);
        }
        buf[r * BP + col] = tf32r(v);
    }
}

__device__ __forceinline__ void zero_acc(float* a, int n) {
    #pragma unroll
    for (int i = 0; i < 64; i++) { if (i < n) a[i] = 0.f; }
}

__global__ void __launch_bounds__(THREADS, 1)
readout_kernel(const float* __restrict__ h0, const float* __restrict__ hT,
               const float* __restrict__ gW0, const float* __restrict__ gb0,
               const float* __restrict__ gW1, const float* __restrict__ gb1,
               const float* __restrict__ gW2, const float* __restrict__ gb2,
               const float* __restrict__ gW3, const float* __restrict__ gb3,
               const float* __restrict__ oW0, const float* __restrict__ ob0,
               const float* __restrict__ oW1, const float* __restrict__ ob1,
               const float* __restrict__ oW2, const float* __restrict__ ob2,
               const float* __restrict__ oW3, const float* __restrict__ ob3,
               float* __restrict__ out) {
    extern __shared__ float sm[];
    float* buf     = sm;                      // 64 x 260
    float* wbuf    = sm + BUF_F;              // staged layer weight (tf32)
    float* bias_sh = wbuf + WBUF_F;           // all 8 biases
    float* mask_sh = bias_sh + BIAS_F;        // 64
    float* out_sh  = mask_sh + 64;            // 256

    const int tid  = threadIdx.x;
    const int lane = tid & 31;
    const int w    = tid >> 5;
    const int mw   = w >> 1, nw = w & 1;
    const int mrow = mw * 16;
    const int g    = lane >> 2, t = lane & 3;

    const size_t row0 = (size_t)blockIdx.x * MTILE;
    const int bidx = (int)(row0 >> 8);        // batch index (64 rows per CTA, 256 per b)

    // --- init small SMEM regions + stage all biases ---
    if (tid < 64) mask_sh[tid] = 0.f;
    out_sh[tid] = 0.f;
    {
        const float* srcs[8] = {gb0, gb1, gb2, gb3, ob0, ob1, ob2, ob3};
        const int    lens[8] = {128, 256, 128, 256, 128, 256, 128, 256};
        int off = 0;
        #pragma unroll
        for (int i = 0; i < 8; i++) {
            if (tid < lens[i]) bias_sh[off + tid] = srcs[i][tid];
            off += lens[i];
        }
    }
    __syncthreads();

    // ================= layer 0 (both paths) =================
    float accG1[32], accV1[32];
    zero_acc(accG1, 32); zero_acc(accV1, 32);

    // h0 tile -> buf (+ mask row sums); gW0[0:256] -> wbuf
    stage_in(buf, h0, row0, mask_sh, tid);
    stage_w<256, 128>(wbuf, gW0, tid);
    __syncthreads();
    if (tid < 64) mask_sh[tid] = (mask_sh[tid] > 0.f) ? 1.f : 0.f;
    mma_layer<256, 128>(buf, wbuf, accG1, mrow, nw, g, t);
    __syncthreads();

    // hT tile -> buf; gW0[256:512] -> wbuf
    stage_in(buf, hT, row0, nullptr, tid);
    stage_w<256, 128>(wbuf, gW0 + 256 * 128, tid);
    __syncthreads();
    mma_layer<256, 128>(buf, wbuf, accG1, mrow, nw, g, t);
    __syncthreads();

    // value L0 reuses hT still in buf
    stage_w<256, 128>(wbuf, oW0, tid);
    __syncthreads();
    mma_layer<256, 128>(buf, wbuf, accV1, mrow, nw, g, t);
    __syncthreads();

    // ================= gate path L1..L3 =================
    float accBig[64];
    float accS[32];

    store_act<128, true>(buf, accG1, bias_sh + 0, mrow, nw, g, t);
    stage_w<128, 256>(wbuf, gW1, tid);
    __syncthreads();
    zero_acc(accBig, 64);
    mma_layer<128, 256>(buf, wbuf, accBig, mrow, nw, g, t);
    __syncthreads();

    store_act<256, true>(buf, accBig, bias_sh + 128, mrow, nw, g, t);
    stage_w<256, 128>(wbuf, gW2, tid);
    __syncthreads();
    zero_acc(accS, 32);
    mma_layer<256, 128>(buf, wbuf, accS, mrow, nw, g, t);
    __syncthreads();

    store_act<128, true>(buf, accS, bias_sh + 384, mrow, nw, g, t);
    stage_w<128, 256>(wbuf, gW3, tid);
    __syncthreads();
    float gsig[64];
    zero_acc(gsig, 64);
    mma_layer<128, 256>(buf, wbuf, gsig, mrow, nw, g, t);
    // sigmoid(gate + gb3) kept in registers; fragment layout will match the
    // value-path final layer exactly.
    #pragma unroll
    for (int nt = 0; nt < 16; nt++) {
        int c = nw * 128 + nt * 8 + 2 * t;
        float b0v = bias_sh[512 + c], b1v = bias_sh[512 + c + 1];
        gsig[4 * nt + 0] = 1.f / (1.f + __expf(-(gsig[4 * nt + 0] + b0v)));
        gsig[4 * nt + 1] = 1.f / (1.f + __expf(-(gsig[4 * nt + 1] + b1v)));
        gsig[4 * nt + 2] = 1.f / (1.f + __expf(-(gsig[4 * nt + 2] + b0v)));
        gsig[4 * nt + 3] = 1.f / (1.f + __expf(-(gsig[4 * nt + 3] + b1v)));
    }
    __syncthreads();   // gate-act reads of buf done before value path overwrites

    // ================= value path L1..L3 =================
    store_act<128, true>(buf, accV1, bias_sh + 768, mrow, nw, g, t);
    stage_w<128, 256>(wbuf, oW1, tid);
    __syncthreads();
    zero_acc(accBig, 64);
    mma_layer<128, 256>(buf, wbuf, accBig, mrow, nw, g, t);
    __syncthreads();

    store_act<256, true>(buf, accBig, bias_sh + 896, mrow, nw, g, t);
    stage_w<256, 128>(wbuf, oW2, tid);
    __syncthreads();
    zero_acc(accS, 32);
    mma_layer<256, 128>(buf, wbuf, accS, mrow, nw, g, t);
    __syncthreads();

    store_act<128, true>(buf, accS, bias_sh + 1152, mrow, nw, g, t);
    stage_w<128, 256>(wbuf, oW3, tid);
    __syncthreads();
    zero_acc(accBig, 64);
    mma_layer<128, 256>(buf, wbuf, accBig, mrow, nw, g, t);   // val final (pre-bias)

    // ================= final combine + node reduction =================
    const float m0 = mask_sh[mrow + g];
    const float m8 = mask_sh[mrow + g + 8];
    #pragma unroll
    for (int nt = 0; nt < 16; nt++) {
        int c = nw * 128 + nt * 8 + 2 * t;
        float b0v = bias_sh[1280 + c], b1v = bias_sh[1280 + c + 1];
        float v0 = accBig[4 * nt + 0] + b0v;
        float v1 = accBig[4 * nt + 1] + b1v;
        float v2 = accBig[4 * nt + 2] + b0v;
        float v3 = accBig[4 * nt + 3] + b1v;
        float s0 = m0 * gsig[4 * nt + 0] * v0 + m8 * gsig[4 * nt + 2] * v2;
        float s1 = m0 * gsig[4 * nt + 1] * v1 + m8 * gsig[4 * nt + 3] * v3;
        // reduce over the 16 rows this warp owns (lanes differing in g)
        s0 += __shfl_xor_sync(0xffffffffu, s0, 4);
        s1 += __shfl_xor_sync(0xffffffffu, s1, 4);
        s0 += __shfl_xor_sync(0xffffffffu, s0, 8);
        s1 += __shfl_xor_sync(0xffffffffu, s1, 8);
        s0 += __shfl_xor_sync(0xffffffffu, s0, 16);
        s1 += __shfl_xor_sync(0xffffffffu, s1, 16);
        if (lane < 4) {                    // g == 0
            atomicAdd(&out_sh[c], s0);
            atomicAdd(&out_sh[c + 1], s1);
        }
    }
    __syncthreads();
    atomicAdd(&out[bidx * 256 + tid], out_sh[tid]);
}

extern "C" void kernel_launch(void* const* d_in, const int* in_sizes, int n_in,
                              void* d_out, int out_size) {
    const float* h0  = (const float*)d_in[0];
    const float* hT  = (const float*)d_in[1];
    const float* gW0 = (const float*)d_in[2];
    const float* gb0 = (const float*)d_in[3];
    const float* gW1 = (const float*)d_in[4];
    const float* gb1 = (const float*)d_in[5];
    const float* gW2 = (const float*)d_in[6];
    const float* gb2 = (const float*)d_in[7];
    const float* gW3 = (const float*)d_in[8];
    const float* gb3 = (const float*)d_in[9];
    const float* oW0 = (const float*)d_in[10];
    const float* ob0 = (const float*)d_in[11];
    const float* oW1 = (const float*)d_in[12];
    const float* ob1 = (const float*)d_in[13];
    const float* oW2 = (const float*)d_in[14];
    const float* ob2 = (const float*)d_in[15];
    const float* oW3 = (const float*)d_in[16];
    const float* ob3 = (const float*)d_in[17];
    float* out = (float*)d_out;

    cudaFuncSetAttribute(readout_kernel,
                         cudaFuncAttributeMaxDynamicSharedMemorySize, SMEM_BYTES);

    // output is accumulated with atomics -> zero it inside the captured graph
    cudaMemsetAsync(d_out, 0, (size_t)out_size * sizeof(float), 0);

    const int n_tiles = (512 * 256) / MTILE;   // 2048 CTAs
    readout_kernel<<<n_tiles, THREADS, SMEM_BYTES>>>(
        h0, hT, gW0, gb0, gW1, gb1, gW2, gb2, gW3, gb3,
        oW0, ob0, oW1, ob1, oW2, ob2, oW3, ob3, out);
}

// round 3
// speedup vs baseline: 2.1083x; 2.1083x over previous
#include <cuda_runtime.h>
#include <cstdint>

// ---------------------------------------------------------------------------
// Fused gated-readout, v2:
//   gate = sigmoid(MLP_g([h0;hT]))   512->128->256->128->256
//   val  = MLP_o(hT)                 256->128->256->128->256
//   out[b,:] = sum_n mask(b,n) * gate(b,n,:) * val(b,n,:)
// B=512, N=256.  One CTA = 64 rows.  tf32 mma.sync m16n8k8.
// v2: weights pre-packed (RNA tf32 + mma-native interleave) by a prep kernel
// into __device__ scratch; main kernel streams 64KB chunks with 16B cp.async
// double buffering; warps own 64 rows (B-fragment reuse 4x) with LDS.64
// conflict-free fragment loads.
// ---------------------------------------------------------------------------

#define THREADS   256
#define BP        264                   // buf pitch (floats): %32==8 -> LDS.64 clean
#define BUF_F     (64 * BP)             // 16896
#define CHUNK_F   16384                 // one weight chunk = 64KB
#define BIAS_F    1536
#define NCHUNKS   18

#define SMEM_F     (BUF_F + 2 * CHUNK_F + BIAS_F + 64)
#define SMEM_BYTES (SMEM_F * 4)         // 205,056 B

__device__ float g_wpack[NCHUNKS * CHUNK_F];   // 1.18 MB packed weights

__device__ __forceinline__ float tf32r(float x) {
    uint32_t v;
    asm("cvt.rna.tf32.f32 %0, %1;" : "=r"(v) : "f"(x));
    return __uint_as_float(v);
}
__device__ __forceinline__ uint32_t fu(float x) { return __float_as_uint(x); }

__device__ __forceinline__ void mma8(float* d,
                                     uint32_t a0, uint32_t a1, uint32_t a2, uint32_t a3,
                                     uint32_t b0, uint32_t b1) {
    asm volatile(
        "mma.sync.aligned.m16n8k8.row.col.f32.tf32.tf32.f32 "
        "{%0,%1,%2,%3}, {%4,%5,%6,%7}, {%8,%9}, {%0,%1,%2,%3};"
        : "+f"(d[0]), "+f"(d[1]), "+f"(d[2]), "+f"(d[3])
        : "r"(a0), "r"(a1), "r"(a2), "r"(a3), "r"(b0), "r"(b1));
}

// ---------------------------------------------------------------------------
// Prep kernel: pack weights as [kb][n][8] with k-interleave p(j): j<4 -> 2j,
// j>=4 -> 2(j-4)+1, so a lane's LDS.64 at 2t yields (k0+t, k0+t+4).
// One block per chunk (18 chunks of 16384 floats).
// ---------------------------------------------------------------------------
__global__ void pack_kernel(const float* __restrict__ gW0, const float* __restrict__ gW1,
                            const float* __restrict__ gW2, const float* __restrict__ gW3,
                            const float* __restrict__ oW0, const float* __restrict__ oW1,
                            const float* __restrict__ oW2, const float* __restrict__ oW3) {
    int c = blockIdx.x;
    const float* W = gW0;
    int N = 128, kbase = 0;
    switch (c >> 1) {
        case 0: W = gW0; N = 128; kbase = 0;   break;   // gate L0 (h0 half)
        case 1: W = gW0; N = 128; kbase = 256; break;   // gate L0 (hT half)
        case 2: W = oW0; N = 128; kbase = 0;   break;   // value L0
        case 3: W = gW1; N = 256; kbase = 0;   break;
        case 4: W = gW2; N = 128; kbase = 0;   break;
        case 5: W = gW3; N = 256; kbase = 0;   break;
        case 6: W = oW1; N = 256; kbase = 0;   break;
        case 7: W = oW2; N = 128; kbase = 0;   break;
        case 8: W = oW3; N = 256; kbase = 0;   break;
    }
    const int KB = (N == 128) ? 16 : 8;        // k-blocks per chunk
    kbase += (c & 1) * KB * 8;
    float* dst = g_wpack + (size_t)c * CHUNK_F;
    for (int idx = threadIdx.x; idx < CHUNK_F; idx += THREADS) {
        int kb  = idx / (N * 8);
        int rem = idx - kb * N * 8;
        int n   = rem >> 3;
        int p   = rem & 7;
        int j   = (p >> 1) + ((p & 1) << 2);   // inverse interleave
        int k   = kbase + kb * 8 + j;
        dst[idx] = tf32r(W[(size_t)k * N + n]);
    }
}

// ---------------------------------------------------------------------------
// cp.async chunk prefetch: flat 64KB blob, 16 x 16B per thread.
// ---------------------------------------------------------------------------
__device__ __forceinline__ void prefetch_chunk(float* dst, int slot, int tid) {
    const float* src = g_wpack + (size_t)slot * CHUNK_F;
    uint32_t sbase = (uint32_t)__cvta_generic_to_shared(dst);
    #pragma unroll
    for (int i = 0; i < 16; i++) {
        int o = tid + i * 256;                 // float4 index
        asm volatile("cp.async.cg.shared.global [%0], [%1], 16;"
                     :: "r"(sbase + o * 16), "l"(src + o * 4));
    }
    asm volatile("cp.async.commit_group;");
}
__device__ __forceinline__ void wait1() { asm volatile("cp.async.wait_group 1;"); }
__device__ __forceinline__ void wait0() { asm volatile("cp.async.wait_group 0;"); }

// ---------------------------------------------------------------------------
// mma over one chunk: acc[64 rows x (N/8 per-warp ntiles)] += bufk @ wc
// warp owns ALL 64 rows (4 m-tiles) x NT n-tiles of 8 cols.
// ---------------------------------------------------------------------------
template <int KB, int N>
__device__ __forceinline__ void mma_chunk(const float* __restrict__ bufk,
                                          const float* __restrict__ wc,
                                          float* acc, int nb, int g, int t) {
    constexpr int NT = (N == 128) ? 2 : 4;
    #pragma unroll 4
    for (int kb = 0; kb < KB; kb++) {
        float2 alo[4], ahi[4];
        #pragma unroll
        for (int mt = 0; mt < 4; mt++) {
            alo[mt] = *(const float2*)&bufk[(mt * 16 + g) * BP + kb * 8 + 2 * t];
            ahi[mt] = *(const float2*)&bufk[(mt * 16 + g + 8) * BP + kb * 8 + 2 * t];
        }
        #pragma unroll
        for (int nt = 0; nt < NT; nt++) {
            float2 b = *(const float2*)&wc[(kb * N + nb + nt * 8 + g) * 8 + 2 * t];
            #pragma unroll
            for (int mt = 0; mt < 4; mt++)
                mma8(acc + (mt * NT + nt) * 4,
                     fu(alo[mt].x), fu(ahi[mt].x), fu(alo[mt].y), fu(ahi[mt].y),
                     fu(b.x), fu(b.y));
        }
    }
}

// Write acc (+bias, ReLU) back to buf as next layer's A operand (interleaved).
template <int N>
__device__ __forceinline__ void store_act(float* __restrict__ buf,
                                          const float* __restrict__ acc,
                                          const float* __restrict__ bias,
                                          int nb, int g, int t) {
    constexpr int NT = (N == 128) ? 2 : 4;
    const int p0 = (t < 2) ? 4 * t     : 4 * t - 7;   // ilv(2t)   : 0,4,1,5
    const int p1 = (t < 2) ? 4 * t + 2 : 4 * t - 5;   // ilv(2t+1) : 2,6,3,7
    #pragma unroll
    for (int nt = 0; nt < NT; nt++) {
        int c  = nb + nt * 8 + 2 * t;
        int kb = (nb >> 3) + nt;
        float b0 = bias[c], b1 = bias[c + 1];
        #pragma unroll
        for (int mt = 0; mt < 4; mt++) {
            int idx = (mt * NT + nt) * 4;
            int r0 = mt * 16 + g, r1 = r0 + 8;
            buf[r0 * BP + kb * 8 + p0] = tf32r(fmaxf(acc[idx + 0] + b0, 0.f));
            buf[r0 * BP + kb * 8 + p1] = tf32r(fmaxf(acc[idx + 1] + b1, 0.f));
            buf[r1 * BP + kb * 8 + p0] = tf32r(fmaxf(acc[idx + 2] + b0, 0.f));
            buf[r1 * BP + kb * 8 + p1] = tf32r(fmaxf(acc[idx + 3] + b1, 0.f));
        }
    }
}

// Stage a [64,256] input tile into buf (tf32 + interleave); optional mask sums.
__device__ __forceinline__ void stage_in(float* __restrict__ buf,
                                         const float* __restrict__ X,
                                         size_t row0, float* mask_sh,
                                         int tid, bool domask) {
    const float4* src = (const float4*)(X + row0 * 256);
    const int lane = tid & 31;
    #pragma unroll 4
    for (int k = 0; k < 16; k++) {
        int f = tid + k * 256;
        float4 v = src[f];
        int r  = f >> 6;
        int kb = (f & 63) >> 1;
        int lo = f & 1;
        float* d = buf + r * BP + kb * 8 + lo;
        d[0] = tf32r(v.x); d[2] = tf32r(v.y); d[4] = tf32r(v.z); d[6] = tf32r(v.w);
        if (domask) {
            float s = v.x + v.y + v.z + v.w;
            s += __shfl_xor_sync(0xffffffffu, s, 16);
            s += __shfl_xor_sync(0xffffffffu, s, 8);
            s += __shfl_xor_sync(0xffffffffu, s, 4);
            s += __shfl_xor_sync(0xffffffffu, s, 2);
            s += __shfl_xor_sync(0xffffffffu, s, 1);
            if (lane == 0) atomicAdd(&mask_sh[r], s);   // whole warp shares row r
        }
    }
}

__device__ __forceinline__ void zero32(float* a) {
    #pragma unroll
    for (int i = 0; i < 32; i++) a[i] = 0.f;
}
__device__ __forceinline__ void zero64(float* a) {
    #pragma unroll
    for (int i = 0; i < 64; i++) a[i] = 0.f;
}

__global__ void __launch_bounds__(THREADS, 1)
readout_kernel(const float* __restrict__ h0, const float* __restrict__ hT,
               const float* __restrict__ gb0, const float* __restrict__ gb1,
               const float* __restrict__ gb2, const float* __restrict__ gb3,
               const float* __restrict__ ob0, const float* __restrict__ ob1,
               const float* __restrict__ ob2, const float* __restrict__ ob3,
               float* __restrict__ out) {
    extern __shared__ float sm[];
    float* buf     = sm;                       // 64 x 264
    float* wb0     = sm + BUF_F;               // chunk slot 0
    float* wb1     = wb0 + CHUNK_F;            // chunk slot 1
    float* bias_sh = wb1 + CHUNK_F;            // 1536
    float* mask_sh = bias_sh + BIAS_F;         // 64

    const int tid  = threadIdx.x;
    const int lane = tid & 31;
    const int w    = tid >> 5;
    const int g    = lane >> 2, t = lane & 3;
    const int nb128 = w * 16;                  // warp n-base, N=128 layers
    const int nb256 = w * 32;                  // warp n-base, N=256 layers

    const size_t row0 = (size_t)blockIdx.x * 64;
    const int bidx = (int)(row0 >> 8);

    float* wb[2] = {wb0, wb1};

    // init mask + stage biases
    if (tid < 64) mask_sh[tid] = 0.f;
    {
        const float* srcs[8] = {gb0, gb1, gb2, gb3, ob0, ob1, ob2, ob3};
        const int    lens[8] = {128, 256, 128, 256, 128, 256, 128, 256};
        int off = 0;
        #pragma unroll
        for (int i = 0; i < 8; i++) {
            if (tid < lens[i]) bias_sh[off + tid] = srcs[i][tid];
            off += lens[i];
        }
    }
    __syncthreads();

    // kick off first two weight chunks, then stage h0
    prefetch_chunk(wb0, 0, tid);
    prefetch_chunk(wb1, 1, tid);
    stage_in(buf, h0, row0, mask_sh, tid, true);
    __syncthreads();

#define STEP(slot, MMACALL)                                            \
    do {                                                               \
        if ((slot) == NCHUNKS - 1) wait0(); else wait1();              \
        __syncthreads();                                               \
        MMACALL;                                                       \
        __syncthreads();                                               \
        if ((slot) + 2 < NCHUNKS)                                      \
            prefetch_chunk(wb[(slot) & 1], (slot) + 2, tid);           \
    } while (0)

    float accA[32], accV1[32], accB[64], gsig[64];
    zero32(accA);   // gate L0 accumulator
    zero32(accV1);

    // ---- gate L0 (h0 half): slots 0,1 ----
    STEP(0, (mma_chunk<16,128>(buf,       wb0, accA, nb128, g, t)));
    STEP(1, (mma_chunk<16,128>(buf + 128, wb1, accA, nb128, g, t)));

    // swap input tile to hT (visible at slot-2 barrier)
    stage_in(buf, hT, row0, nullptr, tid, false);

    // ---- gate L0 (hT half): slots 2,3 ----
    STEP(2, (mma_chunk<16,128>(buf,       wb0, accA, nb128, g, t)));
    STEP(3, (mma_chunk<16,128>(buf + 128, wb1, accA, nb128, g, t)));

    // ---- value L0 (hT still in buf): slots 4,5 ----
    STEP(4, (mma_chunk<16,128>(buf,       wb0, accV1, nb128, g, t)));
    STEP(5, (mma_chunk<16,128>(buf + 128, wb1, accV1, nb128, g, t)));

    // ---- gate L1: slots 6,7 ----
    store_act<128>(buf, accA, bias_sh + 0, nb128, g, t);
    zero64(accB);
    STEP(6, (mma_chunk<8,256>(buf,      wb0, accB, nb256, g, t)));
    STEP(7, (mma_chunk<8,256>(buf + 64, wb1, accB, nb256, g, t)));

    // ---- gate L2: slots 8,9 ----
    store_act<256>(buf, accB, bias_sh + 128, nb256, g, t);
    zero32(accA);
    STEP(8, (mma_chunk<16,128>(buf,       wb0, accA, nb128, g, t)));
    STEP(9, (mma_chunk<16,128>(buf + 128, wb1, accA, nb128, g, t)));

    // ---- gate L3: slots 10,11 ----
    store_act<128>(buf, accA, bias_sh + 384, nb128, g, t);
    zero64(gsig);
    STEP(10, (mma_chunk<8,256>(buf,      wb0, gsig, nb256, g, t)));
    STEP(11, (mma_chunk<8,256>(buf + 64, wb1, gsig, nb256, g, t)));

    // sigmoid(gate + gb3) in registers
    #pragma unroll
    for (int nt = 0; nt < 4; nt++) {
        int c = nb256 + nt * 8 + 2 * t;
        float b0 = bias_sh[512 + c], b1 = bias_sh[512 + c + 1];
        #pragma unroll
        for (int mt = 0; mt < 4; mt++) {
            int idx = (mt * 4 + nt) * 4;
            gsig[idx + 0] = 1.f / (1.f + __expf(-(gsig[idx + 0] + b0)));
            gsig[idx + 1] = 1.f / (1.f + __expf(-(gsig[idx + 1] + b1)));
            gsig[idx + 2] = 1.f / (1.f + __expf(-(gsig[idx + 2] + b0)));
            gsig[idx + 3] = 1.f / (1.f + __expf(-(gsig[idx + 3] + b1)));
        }
    }

    // ---- value L1: slots 12,13 ----
    store_act<128>(buf, accV1, bias_sh + 768, nb128, g, t);
    zero64(accB);
    STEP(12, (mma_chunk<8,256>(buf,      wb0, accB, nb256, g, t)));
    STEP(13, (mma_chunk<8,256>(buf + 64, wb1, accB, nb256, g, t)));

    // ---- value L2: slots 14,15 ----
    store_act<256>(buf, accB, bias_sh + 896, nb256, g, t);
    zero32(accA);
    STEP(14, (mma_chunk<16,128>(buf,       wb0, accA, nb128, g, t)));
    STEP(15, (mma_chunk<16,128>(buf + 128, wb1, accA, nb128, g, t)));

    // ---- value L3: slots 16,17 ----
    store_act<128>(buf, accA, bias_sh + 1152, nb128, g, t);
    zero64(accB);
    STEP(16, (mma_chunk<8,256>(buf,      wb0, accB, nb256, g, t)));
    STEP(17, (mma_chunk<8,256>(buf + 64, wb1, accB, nb256, g, t)));

    // ---- epilogue: mask * gate * val, reduce over 64 rows, atomic to out ----
    float m0[4], m1[4];
    #pragma unroll
    for (int mt = 0; mt < 4; mt++) {
        m0[mt] = (mask_sh[mt * 16 + g]     > 0.f) ? 1.f : 0.f;
        m1[mt] = (mask_sh[mt * 16 + g + 8] > 0.f) ? 1.f : 0.f;
    }
    #pragma unroll
    for (int nt = 0; nt < 4; nt++) {
        int c = nb256 + nt * 8 + 2 * t;
        float b0 = bias_sh[1280 + c], b1 = bias_sh[1280 + c + 1];
        float s0 = 0.f, s1 = 0.f;
        #pragma unroll
        for (int mt = 0; mt < 4; mt++) {
            int idx = (mt * 4 + nt) * 4;
            s0 += m0[mt] * gsig[idx + 0] * (accB[idx + 0] + b0)
                + m1[mt] * gsig[idx + 2] * (accB[idx + 2] + b0);
            s1 += m0[mt] * gsig[idx + 1] * (accB[idx + 1] + b1)
                + m1[mt] * gsig[idx + 3] * (accB[idx + 3] + b1);
        }
        s0 += __shfl_xor_sync(0xffffffffu, s0, 4);
        s1 += __shfl_xor_sync(0xffffffffu, s1, 4);
        s0 += __shfl_xor_sync(0xffffffffu, s0, 8);
        s1 += __shfl_xor_sync(0xffffffffu, s1, 8);
        s0 += __shfl_xor_sync(0xffffffffu, s0, 16);
        s1 += __shfl_xor_sync(0xffffffffu, s1, 16);
        if (lane < 4) {
            atomicAdd(&out[bidx * 256 + c],     s0);
            atomicAdd(&out[bidx * 256 + c + 1], s1);
        }
    }
#undef STEP
}

extern "C" void kernel_launch(void* const* d_in, const int* in_sizes, int n_in,
                              void* d_out, int out_size) {
    const float* h0  = (const float*)d_in[0];
    const float* hT  = (const float*)d_in[1];
    const float* gW0 = (const float*)d_in[2];
    const float* gb0 = (const float*)d_in[3];
    const float* gW1 = (const float*)d_in[4];
    const float* gb1 = (const float*)d_in[5];
    const float* gW2 = (const float*)d_in[6];
    const float* gb2 = (const float*)d_in[7];
    const float* gW3 = (const float*)d_in[8];
    const float* gb3 = (const float*)d_in[9];
    const float* oW0 = (const float*)d_in[10];
    const float* ob0 = (const float*)d_in[11];
    const float* oW1 = (const float*)d_in[12];
    const float* ob1 = (const float*)d_in[13];
    const float* oW2 = (const float*)d_in[14];
    const float* ob2 = (const float*)d_in[15];
    const float* oW3 = (const float*)d_in[16];
    const float* ob3 = (const float*)d_in[17];
    float* out = (float*)d_out;

    cudaFuncSetAttribute(readout_kernel,
                         cudaFuncAttributeMaxDynamicSharedMemorySize, SMEM_BYTES);

    cudaMemsetAsync(d_out, 0, (size_t)out_size * sizeof(float), 0);
    pack_kernel<<<NCHUNKS, THREADS>>>(gW0, gW1, gW2, gW3, oW0, oW1, oW2, oW3);

    readout_kernel<<<2048, THREADS, SMEM_BYTES>>>(
        h0, hT, gb0, gb1, gb2, gb3, ob0, ob1, ob2, ob3, out);
}

// round 5
// speedup vs baseline: 2.1114x; 1.0015x over previous
#include <cuda_runtime.h>
#include <cstdint>

// ---------------------------------------------------------------------------
// Fused gated-readout, v2:
//   gate = sigmoid(MLP_g([h0;hT]))   512->128->256->128->256
//   val  = MLP_o(hT)                 256->128->256->128->256
//   out[b,:] = sum_n mask(b,n) * gate(b,n,:) * val(b,n,:)
// B=512, N=256.  One CTA = 64 rows.  tf32 mma.sync m16n8k8.
// v2: weights pre-packed (RNA tf32 + mma-native interleave) by a prep kernel
// into __device__ scratch; main kernel streams 64KB chunks with 16B cp.async
// double buffering; warps own 64 rows (B-fragment reuse 4x) with LDS.64
// conflict-free fragment loads.
// ---------------------------------------------------------------------------

#define THREADS   256
#define BP        264                   // buf pitch (floats): %32==8 -> LDS.64 clean
#define BUF_F     (64 * BP)             // 16896
#define CHUNK_F   16384                 // one weight chunk = 64KB
#define BIAS_F    1536
#define NCHUNKS   18

#define SMEM_F     (BUF_F + 2 * CHUNK_F + BIAS_F + 64)
#define SMEM_BYTES (SMEM_F * 4)         // 205,056 B

__device__ float g_wpack[NCHUNKS * CHUNK_F];   // 1.18 MB packed weights

__device__ __forceinline__ float tf32r(float x) {
    uint32_t v;
    asm("cvt.rna.tf32.f32 %0, %1;" : "=r"(v) : "f"(x));
    return __uint_as_float(v);
}
__device__ __forceinline__ uint32_t fu(float x) { return __float_as_uint(x); }

__device__ __forceinline__ void mma8(float* d,
                                     uint32_t a0, uint32_t a1, uint32_t a2, uint32_t a3,
                                     uint32_t b0, uint32_t b1) {
    asm volatile(
        "mma.sync.aligned.m16n8k8.row.col.f32.tf32.tf32.f32 "
        "{%0,%1,%2,%3}, {%4,%5,%6,%7}, {%8,%9}, {%0,%1,%2,%3};"
        : "+f"(d[0]), "+f"(d[1]), "+f"(d[2]), "+f"(d[3])
        : "r"(a0), "r"(a1), "r"(a2), "r"(a3), "r"(b0), "r"(b1));
}

// ---------------------------------------------------------------------------
// Prep kernel: pack weights as [kb][n][8] with k-interleave p(j): j<4 -> 2j,
// j>=4 -> 2(j-4)+1, so a lane's LDS.64 at 2t yields (k0+t, k0+t+4).
// One block per chunk (18 chunks of 16384 floats).
// ---------------------------------------------------------------------------
__global__ void pack_kernel(const float* __restrict__ gW0, const float* __restrict__ gW1,
                            const float* __restrict__ gW2, const float* __restrict__ gW3,
                            const float* __restrict__ oW0, const float* __restrict__ oW1,
                            const float* __restrict__ oW2, const float* __restrict__ oW3) {
    int c = blockIdx.x;
    const float* W = gW0;
    int N = 128, kbase = 0;
    switch (c >> 1) {
        case 0: W = gW0; N = 128; kbase = 0;   break;   // gate L0 (h0 half)
        case 1: W = gW0; N = 128; kbase = 256; break;   // gate L0 (hT half)
        case 2: W = oW0; N = 128; kbase = 0;   break;   // value L0
        case 3: W = gW1; N = 256; kbase = 0;   break;
        case 4: W = gW2; N = 128; kbase = 0;   break;
        case 5: W = gW3; N = 256; kbase = 0;   break;
        case 6: W = oW1; N = 256; kbase = 0;   break;
        case 7: W = oW2; N = 128; kbase = 0;   break;
        case 8: W = oW3; N = 256; kbase = 0;   break;
    }
    const int KB = (N == 128) ? 16 : 8;        // k-blocks per chunk
    kbase += (c & 1) * KB * 8;
    float* dst = g_wpack + (size_t)c * CHUNK_F;
    for (int idx = threadIdx.x; idx < CHUNK_F; idx += THREADS) {
        int kb  = idx / (N * 8);
        int rem = idx - kb * N * 8;
        int n   = rem >> 3;
        int p   = rem & 7;
        int j   = (p >> 1) + ((p & 1) << 2);   // inverse interleave
        int k   = kbase + kb * 8 + j;
        dst[idx] = tf32r(W[(size_t)k * N + n]);
    }
}

// ---------------------------------------------------------------------------
// cp.async chunk prefetch: flat 64KB blob, 16 x 16B per thread.
// ---------------------------------------------------------------------------
__device__ __forceinline__ void prefetch_chunk(float* dst, int slot, int tid) {
    const float* src = g_wpack + (size_t)slot * CHUNK_F;
    uint32_t sbase = (uint32_t)__cvta_generic_to_shared(dst);
    #pragma unroll
    for (int i = 0; i < 16; i++) {
        int o = tid + i * 256;                 // float4 index
        asm volatile("cp.async.cg.shared.global [%0], [%1], 16;"
                     :: "r"(sbase + o * 16), "l"(src + o * 4));
    }
    asm volatile("cp.async.commit_group;");
}
__device__ __forceinline__ void wait1() { asm volatile("cp.async.wait_group 1;"); }
__device__ __forceinline__ void wait0() { asm volatile("cp.async.wait_group 0;"); }

// ---------------------------------------------------------------------------
// mma over one chunk: acc[64 rows x (N/8 per-warp ntiles)] += bufk @ wc
// warp owns ALL 64 rows (4 m-tiles) x NT n-tiles of 8 cols.
// ---------------------------------------------------------------------------
template <int KB, int N>
__device__ __forceinline__ void mma_chunk(const float* __restrict__ bufk,
                                          const float* __restrict__ wc,
                                          float* acc, int nb, int g, int t) {
    constexpr int NT = (N == 128) ? 2 : 4;
    #pragma unroll 4
    for (int kb = 0; kb < KB; kb++) {
        float2 alo[4], ahi[4];
        #pragma unroll
        for (int mt = 0; mt < 4; mt++) {
            alo[mt] = *(const float2*)&bufk[(mt * 16 + g) * BP + kb * 8 + 2 * t];
            ahi[mt] = *(const float2*)&bufk[(mt * 16 + g + 8) * BP + kb * 8 + 2 * t];
        }
        #pragma unroll
        for (int nt = 0; nt < NT; nt++) {
            float2 b = *(const float2*)&wc[(kb * N + nb + nt * 8 + g) * 8 + 2 * t];
            #pragma unroll
            for (int mt = 0; mt < 4; mt++)
                mma8(acc + (mt * NT + nt) * 4,
                     fu(alo[mt].x), fu(ahi[mt].x), fu(alo[mt].y), fu(ahi[mt].y),
                     fu(b.x), fu(b.y));
        }
    }
}

// Write acc (+bias, ReLU) back to buf as next layer's A operand (interleaved).
template <int N>
__device__ __forceinline__ void store_act(float* __restrict__ buf,
                                          const float* __restrict__ acc,
                                          const float* __restrict__ bias,
                                          int nb, int g, int t) {
    constexpr int NT = (N == 128) ? 2 : 4;
    const int p0 = (t < 2) ? 4 * t     : 4 * t - 7;   // ilv(2t)   : 0,4,1,5
    const int p1 = (t < 2) ? 4 * t + 2 : 4 * t - 5;   // ilv(2t+1) : 2,6,3,7
    #pragma unroll
    for (int nt = 0; nt < NT; nt++) {
        int c  = nb + nt * 8 + 2 * t;
        int kb = (nb >> 3) + nt;
        float b0 = bias[c], b1 = bias[c + 1];
        #pragma unroll
        for (int mt = 0; mt < 4; mt++) {
            int idx = (mt * NT + nt) * 4;
            int r0 = mt * 16 + g, r1 = r0 + 8;
            buf[r0 * BP + kb * 8 + p0] = tf32r(fmaxf(acc[idx + 0] + b0, 0.f));
            buf[r0 * BP + kb * 8 + p1] = tf32r(fmaxf(acc[idx + 1] + b1, 0.f));
            buf[r1 * BP + kb * 8 + p0] = tf32r(fmaxf(acc[idx + 2] + b0, 0.f));
            buf[r1 * BP + kb * 8 + p1] = tf32r(fmaxf(acc[idx + 3] + b1, 0.f));
        }
    }
}

// Stage a [64,256] input tile into buf (tf32 + interleave); optional mask sums.
__device__ __forceinline__ void stage_in(float* __restrict__ buf,
                                         const float* __restrict__ X,
                                         size_t row0, float* mask_sh,
                                         int tid, bool domask) {
    const float4* src = (const float4*)(X + row0 * 256);
    const int lane = tid & 31;
    #pragma unroll 4
    for (int k = 0; k < 16; k++) {
        int f = tid + k * 256;
        float4 v = src[f];
        int r  = f >> 6;
        int kb = (f & 63) >> 1;
        int lo = f & 1;
        float* d = buf + r * BP + kb * 8 + lo;
        d[0] = tf32r(v.x); d[2] = tf32r(v.y); d[4] = tf32r(v.z); d[6] = tf32r(v.w);
        if (domask) {
            float s = v.x + v.y + v.z + v.w;
            s += __shfl_xor_sync(0xffffffffu, s, 16);
            s += __shfl_xor_sync(0xffffffffu, s, 8);
            s += __shfl_xor_sync(0xffffffffu, s, 4);
            s += __shfl_xor_sync(0xffffffffu, s, 2);
            s += __shfl_xor_sync(0xffffffffu, s, 1);
            if (lane == 0) atomicAdd(&mask_sh[r], s);   // whole warp shares row r
        }
    }
}

__device__ __forceinline__ void zero32(float* a) {
    #pragma unroll
    for (int i = 0; i < 32; i++) a[i] = 0.f;
}
__device__ __forceinline__ void zero64(float* a) {
    #pragma unroll
    for (int i = 0; i < 64; i++) a[i] = 0.f;
}

__global__ void __launch_bounds__(THREADS, 1)
readout_kernel(const float* __restrict__ h0, const float* __restrict__ hT,
               const float* __restrict__ gb0, const float* __restrict__ gb1,
               const float* __restrict__ gb2, const float* __restrict__ gb3,
               const float* __restrict__ ob0, const float* __restrict__ ob1,
               const float* __restrict__ ob2, const float* __restrict__ ob3,
               float* __restrict__ out) {
    extern __shared__ float sm[];
    float* buf     = sm;                       // 64 x 264
    float* wb0     = sm + BUF_F;               // chunk slot 0
    float* wb1     = wb0 + CHUNK_F;            // chunk slot 1
    float* bias_sh = wb1 + CHUNK_F;            // 1536
    float* mask_sh = bias_sh + BIAS_F;         // 64

    const int tid  = threadIdx.x;
    const int lane = tid & 31;
    const int w    = tid >> 5;
    const int g    = lane >> 2, t = lane & 3;
    const int nb128 = w * 16;                  // warp n-base, N=128 layers
    const int nb256 = w * 32;                  // warp n-base, N=256 layers

    const size_t row0 = (size_t)blockIdx.x * 64;
    const int bidx = (int)(row0 >> 8);

    float* wb[2] = {wb0, wb1};

    // init mask + stage biases
    if (tid < 64) mask_sh[tid] = 0.f;
    {
        const float* srcs[8] = {gb0, gb1, gb2, gb3, ob0, ob1, ob2, ob3};
        const int    lens[8] = {128, 256, 128, 256, 128, 256, 128, 256};
        int off = 0;
        #pragma unroll
        for (int i = 0; i < 8; i++) {
            if (tid < lens[i]) bias_sh[off + tid] = srcs[i][tid];
            off += lens[i];
        }
    }
    __syncthreads();

    // kick off first two weight chunks, then stage h0
    prefetch_chunk(wb0, 0, tid);
    prefetch_chunk(wb1, 1, tid);
    stage_in(buf, h0, row0, mask_sh, tid, true);
    __syncthreads();

#define STEP(slot, MMACALL)                                            \
    do {                                                               \
        if ((slot) == NCHUNKS - 1) wait0(); else wait1();              \
        __syncthreads();                                               \
        MMACALL;                                                       \
        __syncthreads();                                               \
        if ((slot) + 2 < NCHUNKS)                                      \
            prefetch_chunk(wb[(slot) & 1], (slot) + 2, tid);           \
    } while (0)

    float accA[32], accV1[32], accB[64], gsig[64];
    zero32(accA);   // gate L0 accumulator
    zero32(accV1);

    // ---- gate L0 (h0 half): slots 0,1 ----
    STEP(0, (mma_chunk<16,128>(buf,       wb0, accA, nb128, g, t)));
    STEP(1, (mma_chunk<16,128>(buf + 128, wb1, accA, nb128, g, t)));

    // swap input tile to hT (visible at slot-2 barrier)
    stage_in(buf, hT, row0, nullptr, tid, false);

    // ---- gate L0 (hT half): slots 2,3 ----
    STEP(2, (mma_chunk<16,128>(buf,       wb0, accA, nb128, g, t)));
    STEP(3, (mma_chunk<16,128>(buf + 128, wb1, accA, nb128, g, t)));

    // ---- value L0 (hT still in buf): slots 4,5 ----
    STEP(4, (mma_chunk<16,128>(buf,       wb0, accV1, nb128, g, t)));
    STEP(5, (mma_chunk<16,128>(buf + 128, wb1, accV1, nb128, g, t)));

    // ---- gate L1: slots 6,7 ----
    store_act<128>(buf, accA, bias_sh + 0, nb128, g, t);
    zero64(accB);
    STEP(6, (mma_chunk<8,256>(buf,      wb0, accB, nb256, g, t)));
    STEP(7, (mma_chunk<8,256>(buf + 64, wb1, accB, nb256, g, t)));

    // ---- gate L2: slots 8,9 ----
    store_act<256>(buf, accB, bias_sh + 128, nb256, g, t);
    zero32(accA);
    STEP(8, (mma_chunk<16,128>(buf,       wb0, accA, nb128, g, t)));
    STEP(9, (mma_chunk<16,128>(buf + 128, wb1, accA, nb128, g, t)));

    // ---- gate L3: slots 10,11 ----
    store_act<128>(buf, accA, bias_sh + 384, nb128, g, t);
    zero64(gsig);
    STEP(10, (mma_chunk<8,256>(buf,      wb0, gsig, nb256, g, t)));
    STEP(11, (mma_chunk<8,256>(buf + 64, wb1, gsig, nb256, g, t)));

    // sigmoid(gate + gb3) in registers
    #pragma unroll
    for (int nt = 0; nt < 4; nt++) {
        int c = nb256 + nt * 8 + 2 * t;
        float b0 = bias_sh[512 + c], b1 = bias_sh[512 + c + 1];
        #pragma unroll
        for (int mt = 0; mt < 4; mt++) {
            int idx = (mt * 4 + nt) * 4;
            gsig[idx + 0] = 1.f / (1.f + __expf(-(gsig[idx + 0] + b0)));
            gsig[idx + 1] = 1.f / (1.f + __expf(-(gsig[idx + 1] + b1)));
            gsig[idx + 2] = 1.f / (1.f + __expf(-(gsig[idx + 2] + b0)));
            gsig[idx + 3] = 1.f / (1.f + __expf(-(gsig[idx + 3] + b1)));
        }
    }

    // ---- value L1: slots 12,13 ----
    store_act<128>(buf, accV1, bias_sh + 768, nb128, g, t);
    zero64(accB);
    STEP(12, (mma_chunk<8,256>(buf,      wb0, accB, nb256, g, t)));
    STEP(13, (mma_chunk<8,256>(buf + 64, wb1, accB, nb256, g, t)));

    // ---- value L2: slots 14,15 ----
    store_act<256>(buf, accB, bias_sh + 896, nb256, g, t);
    zero32(accA);
    STEP(14, (mma_chunk<16,128>(buf,       wb0, accA, nb128, g, t)));
    STEP(15, (mma_chunk<16,128>(buf + 128, wb1, accA, nb128, g, t)));

    // ---- value L3: slots 16,17 ----
    store_act<128>(buf, accA, bias_sh + 1152, nb128, g, t);
    zero64(accB);
    STEP(16, (mma_chunk<8,256>(buf,      wb0, accB, nb256, g, t)));
    STEP(17, (mma_chunk<8,256>(buf + 64, wb1, accB, nb256, g, t)));

    // ---- epilogue: mask * gate * val, reduce over 64 rows, atomic to out ----
    float m0[4], m1[4];
    #pragma unroll
    for (int mt = 0; mt < 4; mt++) {
        m0[mt] = (mask_sh[mt * 16 + g]     > 0.f) ? 1.f : 0.f;
        m1[mt] = (mask_sh[mt * 16 + g + 8] > 0.f) ? 1.f : 0.f;
    }
    #pragma unroll
    for (int nt = 0; nt < 4; nt++) {
        int c = nb256 + nt * 8 + 2 * t;
        float b0 = bias_sh[1280 + c], b1 = bias_sh[1280 + c + 1];
        float s0 = 0.f, s1 = 0.f;
        #pragma unroll
        for (int mt = 0; mt < 4; mt++) {
            int idx = (mt * 4 + nt) * 4;
            s0 += m0[mt] * gsig[idx + 0] * (accB[idx + 0] + b0)
                + m1[mt] * gsig[idx + 2] * (accB[idx + 2] + b0);
            s1 += m0[mt] * gsig[idx + 1] * (accB[idx + 1] + b1)
                + m1[mt] * gsig[idx + 3] * (accB[idx + 3] + b1);
        }
        s0 += __shfl_xor_sync(0xffffffffu, s0, 4);
        s1 += __shfl_xor_sync(0xffffffffu, s1, 4);
        s0 += __shfl_xor_sync(0xffffffffu, s0, 8);
        s1 += __shfl_xor_sync(0xffffffffu, s1, 8);
        s0 += __shfl_xor_sync(0xffffffffu, s0, 16);
        s1 += __shfl_xor_sync(0xffffffffu, s1, 16);
        if (lane < 4) {
            atomicAdd(&out[bidx * 256 + c],     s0);
            atomicAdd(&out[bidx * 256 + c + 1], s1);
        }
    }
#undef STEP
}

extern "C" void kernel_launch(void* const* d_in, const int* in_sizes, int n_in,
                              void* d_out, int out_size) {
    const float* h0  = (const float*)d_in[0];
    const float* hT  = (const float*)d_in[1];
    const float* gW0 = (const float*)d_in[2];
    const float* gb0 = (const float*)d_in[3];
    const float* gW1 = (const float*)d_in[4];
    const float* gb1 = (const float*)d_in[5];
    const float* gW2 = (const float*)d_in[6];
    const float* gb2 = (const float*)d_in[7];
    const float* gW3 = (const float*)d_in[8];
    const float* gb3 = (const float*)d_in[9];
    const float* oW0 = (const float*)d_in[10];
    const float* ob0 = (const float*)d_in[11];
    const float* oW1 = (const float*)d_in[12];
    const float* ob1 = (const float*)d_in[13];
    const float* oW2 = (const float*)d_in[14];
    const float* ob2 = (const float*)d_in[15];
    const float* oW3 = (const float*)d_in[16];
    const float* ob3 = (const float*)d_in[17];
    float* out = (float*)d_out;

    cudaFuncSetAttribute(readout_kernel,
                         cudaFuncAttributeMaxDynamicSharedMemorySize, SMEM_BYTES);

    cudaMemsetAsync(d_out, 0, (size_t)out_size * sizeof(float), 0);
    pack_kernel<<<NCHUNKS, THREADS>>>(gW0, gW1, gW2, gW3, oW0, oW1, oW2, oW3);

    readout_kernel<<<2048, THREADS, SMEM_BYTES>>>(
        h0, hT, gb0, gb1, gb2, gb3, ob0, ob1, ob2, ob3, out);
}

// round 7
// speedup vs baseline: 2.7917x; 1.3222x over previous
#include <cuda_runtime.h>
#include <cuda_fp16.h>
#include <cstdint>

// ---------------------------------------------------------------------------
// Fused gated-readout v4 (fp16 mma.sync m16n8k16, 2 CTAs/SM):
//   gate = sigmoid(MLP_g([h0;hT]))   512->128->256->128->256
//   val  = MLP_o(hT)                 256->128->256->128->256
//   out[b,:] = sum_n mask(b,n) * gate(b,n,:) * val(b,n,:)
// One CTA = 64 rows, 256 threads, 8 warps (each warp owns all 64 rows x its
// n-slice).  Weights pre-packed (fp16 + fragment interleave) and streamed as
// flat 16KB cp.async chunks, double buffered.  Gate sigmoid parked in SMEM as
// fp16 (kills the 128-reg accumulator wall -> 2 CTAs/SM).
// ---------------------------------------------------------------------------

#define THREADS     256
#define NCHUNK      36
#define CHUNK_BYTES 16384
#define BP          528            // row pitch (bytes) in buf / gpark

#define BUF_OFF     0              // 64 x 528 = 33792
#define GP_OFF      33792          // gate park / value-act park, 64 x 528
#define SLOT_OFF    67584          // 2 x 16384 weight slots
#define BIAS_OFF    100352         // 1536 fp32
#define MASK_OFF    106496         // 64 fp32
#define SMEM_BYTES  106752

__device__ __align__(16) unsigned short g_wpack[NCHUNK * 8192];

// fragment k-interleave inside a 16-k block: position p holds k = O16[p]
__constant__ int O16[16] = {0,1,8,9, 2,3,10,11, 4,5,12,13, 6,7,14,15};
__constant__ unsigned short c_aoff[NCHUNK] = {
    0,128,256,384,  0,128,256,384,  0,128,256,384,   // gW0(h0), gW0(hT), oW0
    0,64,128,192,   0,128,256,384,  0,64,128,192,    // gW1, gW2, gW3
    0,64,128,192,   0,128,256,384,  0,64,128,192};   // oW1, oW2, oW3

__device__ __forceinline__ void hmma(float* d,
                                     uint32_t a0, uint32_t a1, uint32_t a2, uint32_t a3,
                                     uint32_t b0, uint32_t b1) {
    asm volatile(
        "mma.sync.aligned.m16n8k16.row.col.f32.f16.f16.f32 "
        "{%0,%1,%2,%3}, {%4,%5,%6,%7}, {%8,%9}, {%0,%1,%2,%3};"
        : "+f"(d[0]), "+f"(d[1]), "+f"(d[2]), "+f"(d[3])
        : "r"(a0), "r"(a1), "r"(a2), "r"(a3), "r"(b0), "r"(b1));
}

__device__ __forceinline__ int posu(int u) { return (u < 4) ? 4 * u : 4 * (u - 4) + 2; }

// ---------------------------------------------------------------------------
// pack: 36 chunks of 8192 halves, layout [kb][n][16 interleaved k] — one
// LDS.64 per lane yields a complete A- or B-fragment half.
// ---------------------------------------------------------------------------
__global__ void pack_kernel(const float* __restrict__ gW0, const float* __restrict__ gW1,
                            const float* __restrict__ gW2, const float* __restrict__ gW3,
                            const float* __restrict__ oW0, const float* __restrict__ oW1,
                            const float* __restrict__ oW2, const float* __restrict__ oW3) {
    int c = blockIdx.x;
    const float* W; int Nl, ks;
    if (c < 8)       { W = gW0; Nl = 128; ks = c * 64; }
    else if (c < 12) { W = oW0; Nl = 128; ks = (c - 8) * 64; }
    else if (c < 16) { W = gW1; Nl = 256; ks = (c - 12) * 32; }
    else if (c < 20) { W = gW2; Nl = 128; ks = (c - 16) * 64; }
    else if (c < 24) { W = gW3; Nl = 256; ks = (c - 20) * 32; }
    else if (c < 28) { W = oW1; Nl = 256; ks = (c - 24) * 32; }
    else if (c < 32) { W = oW2; Nl = 128; ks = (c - 28) * 64; }
    else             { W = oW3; Nl = 256; ks = (c - 32) * 32; }
    unsigned short* dst = g_wpack + (size_t)c * 8192;
    for (int i = threadIdx.x; i < 8192; i += blockDim.x) {
        int kb  = i / (Nl * 16);
        int rem = i - kb * Nl * 16;
        int n   = rem >> 4;
        int p   = rem & 15;
        int k   = ks + kb * 16 + O16[p];
        dst[i] = __half_as_ushort(__float2half_rn(W[(size_t)k * Nl + n]));
    }
}

// ---------------------------------------------------------------------------
__device__ __forceinline__ void prefetch(char* smdst, int idx, int tid) {
    const char* src = (const char*)g_wpack + (size_t)idx * CHUNK_BYTES;
    uint32_t sb = (uint32_t)__cvta_generic_to_shared(smdst);
    #pragma unroll
    for (int i = 0; i < 4; i++) {
        int o = (tid + i * 256) * 16;
        asm volatile("cp.async.cg.shared.global [%0], [%1], 16;" :: "r"(sb + o), "l"(src + o));
    }
    asm volatile("cp.async.commit_group;");
}

// acc[4mt x NT x 4] += buf[64, k] @ W[k, warp n-slice];  KB 16-k blocks.
template <int KB, int NT>
__device__ __forceinline__ void mma_chunk(const char* __restrict__ bA,
                                          const char* __restrict__ wc,
                                          float* acc, int nbB, int g, int t) {
    constexpr int NB = (NT == 2 ? 128 : 256) * 32;   // per-kb byte stride in chunk
    #pragma unroll
    for (int kb = 0; kb < KB; kb++) {
        uint2 alo[4], ahi[4];
        const char* ar = bA + kb * 32 + t * 8;
        #pragma unroll
        for (int mt = 0; mt < 4; mt++) {
            alo[mt] = *(const uint2*)(ar + (mt * 16 + g) * BP);
            ahi[mt] = *(const uint2*)(ar + (mt * 16 + g + 8) * BP);
        }
        const char* br = wc + kb * NB + nbB + g * 32 + t * 8;
        #pragma unroll
        for (int nt = 0; nt < NT; nt++) {
            uint2 b = *(const uint2*)(br + nt * 256);
            #pragma unroll
            for (int mt = 0; mt < 4; mt++)
                hmma(acc + (mt * NT + nt) * 4,
                     alo[mt].x, ahi[mt].x, alo[mt].y, ahi[mt].y, b.x, b.y);
        }
    }
}

// relu(acc + bias) -> dst as next layer's interleaved fp16 A operand
template <int NT>
__device__ __forceinline__ void store_act(char* __restrict__ dst, const float* acc,
                                          const float* __restrict__ bias,
                                          int nb, int g, int t) {
    #pragma unroll
    for (int nt = 0; nt < NT; nt++) {
        int c = nb + nt * 8 + 2 * t;
        int off = (c >> 4) * 32 + posu((c & 15) >> 1) * 2;
        float b0 = bias[c], b1 = bias[c + 1];
        #pragma unroll
        for (int mt = 0; mt < 4; mt++) {
            int id = (mt * NT + nt) * 4;
            int r0 = mt * 16 + g, r1 = r0 + 8;
            *(__half2*)(dst + r0 * BP + off) =
                __floats2half2_rn(fmaxf(acc[id] + b0, 0.f), fmaxf(acc[id + 1] + b1, 0.f));
            *(__half2*)(dst + r1 * BP + off) =
                __floats2half2_rn(fmaxf(acc[id + 2] + b0, 0.f), fmaxf(acc[id + 3] + b1, 0.f));
        }
    }
}

// fp32 global tile -> interleaved fp16 A buffer (+ optional mask row sums)
__device__ __forceinline__ void stage_in(char* __restrict__ buf, const float* __restrict__ X,
                                         size_t row0, float* mask_sh, int tid, bool domask) {
    int r = tid >> 2, q = tid & 3;
    const float4* src = (const float4*)(X + (row0 + r) * 256) + q * 16;
    float s = 0.f;
    #pragma unroll
    for (int i = 0; i < 16; i++) {
        float4 v = src[i];
        if (domask) s += v.x + v.y + v.z + v.w;
        int c = q * 64 + 4 * i;
        int u = (c & 15) >> 1;                        // even
        char* base = buf + r * BP + (c >> 4) * 32;
        *(__half2*)(base + posu(u) * 2)     = __floats2half2_rn(v.x, v.y);
        *(__half2*)(base + posu(u + 1) * 2) = __floats2half2_rn(v.z, v.w);
    }
    if (domask) {
        s += __shfl_xor_sync(0xffffffffu, s, 1);
        s += __shfl_xor_sync(0xffffffffu, s, 2);
        if (q == 0) mask_sh[r] = (s > 0.f) ? 1.f : 0.f;
    }
}

__device__ __forceinline__ void zero_n(float* a, int n) {
    #pragma unroll
    for (int i = 0; i < 64; i++) if (i < n) a[i] = 0.f;
}

__global__ void __launch_bounds__(THREADS, 2)
readout_kernel(const float* __restrict__ h0, const float* __restrict__ hT,
               const float* __restrict__ gb0, const float* __restrict__ gb1,
               const float* __restrict__ gb2, const float* __restrict__ gb3,
               const float* __restrict__ ob0, const float* __restrict__ ob1,
               const float* __restrict__ ob2, const float* __restrict__ ob3,
               float* __restrict__ out) {
    extern __shared__ __align__(16) char sm[];
    char*  buf     = sm + BUF_OFF;
    char*  gpark   = sm + GP_OFF;
    float* bias_sh = (float*)(sm + BIAS_OFF);
    float* mask_sh = (float*)(sm + MASK_OFF);

    const int tid  = threadIdx.x;
    const int lane = tid & 31;
    const int w    = tid >> 5;
    const int g    = lane >> 2, t = lane & 3;
    const int nb128 = w * 16, nb256 = w * 32;

    const size_t row0 = (size_t)blockIdx.x * 64;
    const int bidx = (int)(blockIdx.x >> 2);

    // stage biases
    {
        const float* srcs[8] = {gb0, gb1, gb2, gb3, ob0, ob1, ob2, ob3};
        const int    lens[8] = {128, 256, 128, 256, 128, 256, 128, 256};
        int off = 0;
        #pragma unroll
        for (int i = 0; i < 8; i++) {
            if (tid < lens[i]) bias_sh[off + tid] = srcs[i][tid];
            off += lens[i];
        }
    }

    prefetch(sm + SLOT_OFF, 0, tid);
    prefetch(sm + SLOT_OFF + CHUNK_BYTES, 1, tid);
    stage_in(buf, h0, row0, mask_sh, tid, true);
    __syncthreads();

    float accA[32], accV[32], accB[64];
    zero_n(accA, 32); zero_n(accV, 32);

    for (int idx = 0; idx < NCHUNK; idx++) {
        if (idx == NCHUNK - 1) asm volatile("cp.async.wait_group 0;");
        else                   asm volatile("cp.async.wait_group 1;");
        __syncthreads();
        char* slot = sm + SLOT_OFF + (idx & 1) * CHUNK_BYTES;
        const char* bA = buf + c_aoff[idx];

        if (idx < 8)       mma_chunk<4,2>(bA, slot, accA, nb128 * 32, g, t);  // gate L0
        else if (idx < 12) mma_chunk<4,2>(bA, slot, accV, nb128 * 32, g, t);  // value L0
        else if (idx < 16) mma_chunk<2,4>(bA, slot, accB, nb256 * 32, g, t);  // gate L1
        else if (idx < 20) mma_chunk<4,2>(bA, slot, accA, nb128 * 32, g, t);  // gate L2
        else if (idx < 24) mma_chunk<2,4>(bA, slot, accB, nb256 * 32, g, t);  // gate L3
        else if (idx < 28) mma_chunk<2,4>(bA, slot, accB, nb256 * 32, g, t);  // value L1
        else if (idx < 32) mma_chunk<4,2>(bA, slot, accA, nb128 * 32, g, t);  // value L2
        else               mma_chunk<2,4>(bA, slot, accB, nb256 * 32, g, t);  // value L3

        __syncthreads();
        if (idx + 2 < NCHUNK) prefetch(slot, idx + 2, tid);

        if (idx == 3) {                                    // h0 -> hT restage
            stage_in(buf, hT, row0, nullptr, tid, false);
        } else if (idx == 11) {                            // gate act -> buf, value act -> park
            store_act<2>(buf,   accA, bias_sh + 0,   nb128, g, t);
            store_act<2>(gpark, accV, bias_sh + 768, nb128, g, t);
            zero_n(accB, 64);
        } else if (idx == 15) {
            store_act<4>(buf, accB, bias_sh + 128, nb256, g, t);
            zero_n(accA, 32);
        } else if (idx == 19) {
            store_act<2>(buf, accA, bias_sh + 384, nb128, g, t);
            zero_n(accB, 64);
        } else if (idx == 23) {
            // copy parked value act (bytes [0,256) per row) into buf
            #pragma unroll
            for (int j = 0; j < 4; j++) {
                int tt = tid + j * 256;
                int r = tt >> 4, off = (tt & 15) * 16;
                *(float4*)(buf + r * BP + off) = *(const float4*)(gpark + r * BP + off);
            }
            __syncthreads();
            // sigmoid(gate + gb3) -> gpark (fp16)
            #pragma unroll
            for (int nt = 0; nt < 4; nt++) {
                int c = nb256 + nt * 8 + 2 * t;
                int off = (c >> 4) * 32 + posu((c & 15) >> 1) * 2;
                float b0 = bias_sh[512 + c], b1 = bias_sh[512 + c + 1];
                #pragma unroll
                for (int mt = 0; mt < 4; mt++) {
                    int id = (mt * 4 + nt) * 4;
                    int r0 = mt * 16 + g, r1 = r0 + 8;
                    float s0 = 1.f / (1.f + __expf(-(accB[id]     + b0)));
                    float s1 = 1.f / (1.f + __expf(-(accB[id + 1] + b1)));
                    float s2 = 1.f / (1.f + __expf(-(accB[id + 2] + b0)));
                    float s3 = 1.f / (1.f + __expf(-(accB[id + 3] + b1)));
                    *(__half2*)(gpark + r0 * BP + off) = __floats2half2_rn(s0, s1);
                    *(__half2*)(gpark + r1 * BP + off) = __floats2half2_rn(s2, s3);
                }
            }
            zero_n(accB, 64);
        } else if (idx == 27) {
            store_act<4>(buf, accB, bias_sh + 896, nb256, g, t);
            zero_n(accA, 32);
        } else if (idx == 31) {
            store_act<2>(buf, accA, bias_sh + 1152, nb128, g, t);
            zero_n(accB, 64);
        } else if (idx == 35) {                            // combine + reduce
            #pragma unroll
            for (int nt = 0; nt < 4; nt++) {
                int c = nb256 + nt * 8 + 2 * t;
                int off = (c >> 4) * 32 + posu((c & 15) >> 1) * 2;
                float b0 = bias_sh[1280 + c], b1 = bias_sh[1280 + c + 1];
                float s0 = 0.f, s1 = 0.f;
                #pragma unroll
                for (int mt = 0; mt < 4; mt++) {
                    int id = (mt * 4 + nt) * 4;
                    int r0 = mt * 16 + g, r1 = r0 + 8;
                    __half2 hg0 = *(__half2*)(gpark + r0 * BP + off);
                    __half2 hg1 = *(__half2*)(gpark + r1 * BP + off);
                    float m0 = mask_sh[r0], m1 = mask_sh[r1];
                    s0 += m0 * __low2float(hg0)  * (accB[id]     + b0)
                        + m1 * __low2float(hg1)  * (accB[id + 2] + b0);
                    s1 += m0 * __high2float(hg0) * (accB[id + 1] + b1)
                        + m1 * __high2float(hg1) * (accB[id + 3] + b1);
                }
                s0 += __shfl_xor_sync(0xffffffffu, s0, 4);
                s1 += __shfl_xor_sync(0xffffffffu, s1, 4);
                s0 += __shfl_xor_sync(0xffffffffu, s0, 8);
                s1 += __shfl_xor_sync(0xffffffffu, s1, 8);
                s0 += __shfl_xor_sync(0xffffffffu, s0, 16);
                s1 += __shfl_xor_sync(0xffffffffu, s1, 16);
                if (lane < 4) {
                    atomicAdd(&out[bidx * 256 + c],     s0);
                    atomicAdd(&out[bidx * 256 + c + 1], s1);
                }
            }
        }
    }
}

extern "C" void kernel_launch(void* const* d_in, const int* in_sizes, int n_in,
                              void* d_out, int out_size) {
    const float* h0  = (const float*)d_in[0];
    const float* hT  = (const float*)d_in[1];
    const float* gW0 = (const float*)d_in[2];  const float* gb0 = (const float*)d_in[3];
    const float* gW1 = (const float*)d_in[4];  const float* gb1 = (const float*)d_in[5];
    const float* gW2 = (const float*)d_in[6];  const float* gb2 = (const float*)d_in[7];
    const float* gW3 = (const float*)d_in[8];  const float* gb3 = (const float*)d_in[9];
    const float* oW0 = (const float*)d_in[10]; const float* ob0 = (const float*)d_in[11];
    const float* oW1 = (const float*)d_in[12]; const float* ob1 = (const float*)d_in[13];
    const float* oW2 = (const float*)d_in[14]; const float* ob2 = (const float*)d_in[15];
    const float* oW3 = (const float*)d_in[16]; const float* ob3 = (const float*)d_in[17];
    float* out = (float*)d_out;

    cudaFuncSetAttribute(readout_kernel,
                         cudaFuncAttributeMaxDynamicSharedMemorySize, SMEM_BYTES);
    cudaMemsetAsync(d_out, 0, (size_t)out_size * sizeof(float), 0);
    pack_kernel<<<NCHUNK, 256>>>(gW0, gW1, gW2, gW3, oW0, oW1, oW2, oW3);
    readout_kernel<<<2048, THREADS, SMEM_BYTES>>>(
        h0, hT, gb0, gb1, gb2, gb3, ob0, ob1, ob2, ob3, out);
}

// round 8
// speedup vs baseline: 3.0171x; 1.0807x over previous
#include <cuda_runtime.h>
#include <cuda_fp16.h>
#include <cstdint>

// ---------------------------------------------------------------------------
// Fused gated-readout v5 (fp16 mma.sync m16n8k16, 2 CTAs/SM):
//   gate = sigmoid(MLP_g([h0;hT]))   512->128->256->128->256
//   val  = MLP_o(hT)                 256->128->256->128->256
//   out[b,:] = sum_n mask(b,n) * gate(b,n,:) * val(b,n,:)
// One CTA = 64 rows, 256 threads, 8 warps in a (2 M x 4 N) grid: each warp
// owns 32 rows x (32|64) cols -> A redundancy 4x (was 8x).  Row pitch 544
// (== 32 mod 128) makes A-fragment LDS.64 conflict-free.  Weights pre-packed
// (fp16, fragment interleave), streamed as 16KB cp.async chunks, 2 slots.
// Gate sigmoid parked in SMEM as fp16.
// ---------------------------------------------------------------------------

#define THREADS     256
#define NCHUNK      36
#define CHUNK_BYTES 16384
#define BP          544            // row pitch bytes: 544 % 128 == 32 -> clean LDS

#define BUF_OFF     0              // 64 x 544 = 34816
#define GP_OFF      34816          // park buffer, 64 x 544
#define SLOT_OFF    69632          // 2 x 16384 weight slots
#define BIAS_OFF    102400         // 1536 fp32
#define MASK_OFF    108544         // 64 fp32
#define SMEM_BYTES  108800

__device__ __align__(16) unsigned short g_wpack[NCHUNK * 8192];

// fragment k-interleave inside a 16-k block
__constant__ int O16[16] = {0,1,8,9, 2,3,10,11, 4,5,12,13, 6,7,14,15};
__constant__ unsigned short c_aoff[NCHUNK] = {
    0,128,256,384,  0,128,256,384,  0,128,256,384,   // gW0(h0), gW0(hT), oW0
    0,64,128,192,   0,128,256,384,  0,64,128,192,    // gW1, gW2, gW3
    0,64,128,192,   0,128,256,384,  0,64,128,192};   // oW1, oW2, oW3

__device__ __forceinline__ void hmma(float* d,
                                     uint32_t a0, uint32_t a1, uint32_t a2, uint32_t a3,
                                     uint32_t b0, uint32_t b1) {
    asm volatile(
        "mma.sync.aligned.m16n8k16.row.col.f32.f16.f16.f32 "
        "{%0,%1,%2,%3}, {%4,%5,%6,%7}, {%8,%9}, {%0,%1,%2,%3};"
        : "+f"(d[0]), "+f"(d[1]), "+f"(d[2]), "+f"(d[3])
        : "r"(a0), "r"(a1), "r"(a2), "r"(a3), "r"(b0), "r"(b1));
}

__device__ __forceinline__ int posu(int u) { return (u < 4) ? 4 * u : 4 * (u - 4) + 2; }

// ---------------------------------------------------------------------------
__global__ void pack_kernel(const float* __restrict__ gW0, const float* __restrict__ gW1,
                            const float* __restrict__ gW2, const float* __restrict__ gW3,
                            const float* __restrict__ oW0, const float* __restrict__ oW1,
                            const float* __restrict__ oW2, const float* __restrict__ oW3) {
    int c = blockIdx.x;
    const float* W; int Nl, ks;
    if (c < 8)       { W = gW0; Nl = 128; ks = c * 64; }
    else if (c < 12) { W = oW0; Nl = 128; ks = (c - 8) * 64; }
    else if (c < 16) { W = gW1; Nl = 256; ks = (c - 12) * 32; }
    else if (c < 20) { W = gW2; Nl = 128; ks = (c - 16) * 64; }
    else if (c < 24) { W = gW3; Nl = 256; ks = (c - 20) * 32; }
    else if (c < 28) { W = oW1; Nl = 256; ks = (c - 24) * 32; }
    else if (c < 32) { W = oW2; Nl = 128; ks = (c - 28) * 64; }
    else             { W = oW3; Nl = 256; ks = (c - 32) * 32; }
    unsigned short* dst = g_wpack + (size_t)c * 8192;
    for (int i = threadIdx.x; i < 8192; i += blockDim.x) {
        int kb  = i / (Nl * 16);
        int rem = i - kb * Nl * 16;
        int n   = rem >> 4;
        int p   = rem & 15;
        int k   = ks + kb * 16 + O16[p];
        dst[i] = __half_as_ushort(__float2half_rn(W[(size_t)k * Nl + n]));
    }
}

// ---------------------------------------------------------------------------
__device__ __forceinline__ void prefetch(char* smdst, int idx, int tid) {
    const char* src = (const char*)g_wpack + (size_t)idx * CHUNK_BYTES;
    uint32_t sb = (uint32_t)__cvta_generic_to_shared(smdst);
    #pragma unroll
    for (int i = 0; i < 4; i++) {
        int o = (tid + i * 256) * 16;
        asm volatile("cp.async.cg.shared.global [%0], [%1], 16;" :: "r"(sb + o), "l"(src + o));
    }
    asm volatile("cp.async.commit_group;");
}

// acc[2mt x NT x 4] += buf[warp 32-row slice, k] @ W[k, warp n-slice]
template <int KB, int NT>
__device__ __forceinline__ void mma_chunk(const char* __restrict__ bA,
                                          const char* __restrict__ wc,
                                          float* acc, int mbB, int nbB, int g, int t) {
    constexpr int NB = (NT == 4 ? 128 : 256) * 32;   // per-kb byte stride in chunk
    #pragma unroll
    for (int kb = 0; kb < KB; kb++) {
        uint2 alo[2], ahi[2];
        const char* ar = bA + mbB + g * BP + kb * 32 + t * 8;
        #pragma unroll
        for (int mt = 0; mt < 2; mt++) {
            alo[mt] = *(const uint2*)(ar + (mt * 16) * BP);
            ahi[mt] = *(const uint2*)(ar + (mt * 16 + 8) * BP);
        }
        const char* br = wc + kb * NB + nbB + g * 32 + t * 8;
        #pragma unroll
        for (int nt = 0; nt < NT; nt++) {
            uint2 b = *(const uint2*)(br + nt * 256);
            #pragma unroll
            for (int mt = 0; mt < 2; mt++)
                hmma(acc + (mt * NT + nt) * 4,
                     alo[mt].x, ahi[mt].x, alo[mt].y, ahi[mt].y, b.x, b.y);
        }
    }
}

// relu(acc + bias) -> dst as next layer's interleaved fp16 A operand
template <int NT>
__device__ __forceinline__ void store_act(char* __restrict__ dst, const float* acc,
                                          const float* __restrict__ bias,
                                          int mb, int nb, int g, int t) {
    #pragma unroll
    for (int nt = 0; nt < NT; nt++) {
        int c = nb + nt * 8 + 2 * t;
        int off = (c >> 4) * 32 + posu((c & 15) >> 1) * 2;
        float b0 = bias[c], b1 = bias[c + 1];
        #pragma unroll
        for (int mt = 0; mt < 2; mt++) {
            int id = (mt * NT + nt) * 4;
            int r0 = mb + mt * 16 + g, r1 = r0 + 8;
            *(__half2*)(dst + r0 * BP + off) =
                __floats2half2_rn(fmaxf(acc[id] + b0, 0.f), fmaxf(acc[id + 1] + b1, 0.f));
            *(__half2*)(dst + r1 * BP + off) =
                __floats2half2_rn(fmaxf(acc[id + 2] + b0, 0.f), fmaxf(acc[id + 3] + b1, 0.f));
        }
    }
}

// fp32 global tile -> interleaved fp16 A buffer (+ optional mask row sums)
__device__ __forceinline__ void stage_in(char* __restrict__ buf, const float* __restrict__ X,
                                         size_t row0, float* mask_sh, int tid, bool domask) {
    int r = tid >> 2, q = tid & 3;
    const float4* src = (const float4*)(X + (row0 + r) * 256) + q * 16;
    float s = 0.f;
    #pragma unroll
    for (int i = 0; i < 16; i++) {
        float4 v = src[i];
        if (domask) s += v.x + v.y + v.z + v.w;
        int c = q * 64 + 4 * i;
        int u = (c & 15) >> 1;
        char* base = buf + r * BP + (c >> 4) * 32;
        *(__half2*)(base + posu(u) * 2)     = __floats2half2_rn(v.x, v.y);
        *(__half2*)(base + posu(u + 1) * 2) = __floats2half2_rn(v.z, v.w);
    }
    if (domask) {
        s += __shfl_xor_sync(0xffffffffu, s, 1);
        s += __shfl_xor_sync(0xffffffffu, s, 2);
        if (q == 0) mask_sh[r] = (s > 0.f) ? 1.f : 0.f;
    }
}

__device__ __forceinline__ void zero_n(float* a, int n) {
    #pragma unroll
    for (int i = 0; i < 64; i++) if (i < n) a[i] = 0.f;
}

__global__ void __launch_bounds__(THREADS, 2)
readout_kernel(const float* __restrict__ h0, const float* __restrict__ hT,
               const float* __restrict__ gb0, const float* __restrict__ gb1,
               const float* __restrict__ gb2, const float* __restrict__ gb3,
               const float* __restrict__ ob0, const float* __restrict__ ob1,
               const float* __restrict__ ob2, const float* __restrict__ ob3,
               float* __restrict__ out) {
    extern __shared__ __align__(16) char sm[];
    char*  buf     = sm + BUF_OFF;
    char*  gpark   = sm + GP_OFF;
    float* bias_sh = (float*)(sm + BIAS_OFF);
    float* mask_sh = (float*)(sm + MASK_OFF);

    const int tid  = threadIdx.x;
    const int lane = tid & 31;
    const int w    = tid >> 5;
    const int wm   = w & 1, wn = w >> 1;          // 2 x 4 warp grid
    const int g    = lane >> 2, t = lane & 3;
    const int mb    = wm * 32;                    // warp row base
    const int mbB   = mb * BP;                    // ... in bytes
    const int nb128 = wn * 32, nb256 = wn * 64;   // warp col bases

    const size_t row0 = (size_t)blockIdx.x * 64;
    const int bidx = (int)(blockIdx.x >> 2);

    // stage biases
    {
        const float* srcs[8] = {gb0, gb1, gb2, gb3, ob0, ob1, ob2, ob3};
        const int    lens[8] = {128, 256, 128, 256, 128, 256, 128, 256};
        int off = 0;
        #pragma unroll
        for (int i = 0; i < 8; i++) {
            if (tid < lens[i]) bias_sh[off + tid] = srcs[i][tid];
            off += lens[i];
        }
    }

    prefetch(sm + SLOT_OFF, 0, tid);
    prefetch(sm + SLOT_OFF + CHUNK_BYTES, 1, tid);
    stage_in(buf, h0, row0, mask_sh, tid, true);
    __syncthreads();

    float accA[32], accV[32], accB[64];
    zero_n(accA, 32); zero_n(accV, 32);

    for (int idx = 0; idx < NCHUNK; idx++) {
        if (idx == NCHUNK - 1) asm volatile("cp.async.wait_group 0;");
        else                   asm volatile("cp.async.wait_group 1;");
        __syncthreads();
        char* slot = sm + SLOT_OFF + (idx & 1) * CHUNK_BYTES;
        const char* bA = buf + c_aoff[idx];

        if (idx < 8)       mma_chunk<4,4>(bA, slot, accA, mbB, nb128 * 32, g, t);  // gate L0
        else if (idx < 12) mma_chunk<4,4>(bA, slot, accV, mbB, nb128 * 32, g, t);  // value L0
        else if (idx < 16) mma_chunk<2,8>(bA, slot, accB, mbB, nb256 * 32, g, t);  // gate L1
        else if (idx < 20) mma_chunk<4,4>(bA, slot, accA, mbB, nb128 * 32, g, t);  // gate L2
        else if (idx < 24) mma_chunk<2,8>(bA, slot, accB, mbB, nb256 * 32, g, t);  // gate L3
        else if (idx < 28) mma_chunk<2,8>(bA, slot, accB, mbB, nb256 * 32, g, t);  // value L1
        else if (idx < 32) mma_chunk<4,4>(bA, slot, accA, mbB, nb128 * 32, g, t);  // value L2
        else               mma_chunk<2,8>(bA, slot, accB, mbB, nb256 * 32, g, t);  // value L3

        __syncthreads();
        if (idx + 2 < NCHUNK) prefetch(slot, idx + 2, tid);

        if (idx == 3) {                                    // h0 -> hT restage
            stage_in(buf, hT, row0, nullptr, tid, false);
        } else if (idx == 11) {                            // gate act -> buf, value act -> park
            store_act<4>(buf,   accA, bias_sh + 0,   mb, nb128, g, t);
            store_act<4>(gpark, accV, bias_sh + 768, mb, nb128, g, t);
            zero_n(accB, 64);
        } else if (idx == 15) {
            store_act<8>(buf, accB, bias_sh + 128, mb, nb256, g, t);
            zero_n(accA, 32);
        } else if (idx == 19) {
            store_act<4>(buf, accA, bias_sh + 384, mb, nb128, g, t);
            zero_n(accB, 64);
        } else if (idx == 23) {
            // copy parked value act (bytes [0,256) per row) into buf
            #pragma unroll
            for (int j = 0; j < 4; j++) {
                int tt = tid + j * 256;
                int r = tt >> 4, off = (tt & 15) * 16;
                *(float4*)(buf + r * BP + off) = *(const float4*)(gpark + r * BP + off);
            }
            __syncthreads();
            // sigmoid(gate + gb3) -> gpark (fp16)
            #pragma unroll
            for (int nt = 0; nt < 8; nt++) {
                int c = nb256 + nt * 8 + 2 * t;
                int off = (c >> 4) * 32 + posu((c & 15) >> 1) * 2;
                float b0 = bias_sh[512 + c], b1 = bias_sh[512 + c + 1];
                #pragma unroll
                for (int mt = 0; mt < 2; mt++) {
                    int id = (mt * 8 + nt) * 4;
                    int r0 = mb + mt * 16 + g, r1 = r0 + 8;
                    float s0 = 1.f / (1.f + __expf(-(accB[id]     + b0)));
                    float s1 = 1.f / (1.f + __expf(-(accB[id + 1] + b1)));
                    float s2 = 1.f / (1.f + __expf(-(accB[id + 2] + b0)));
                    float s3 = 1.f / (1.f + __expf(-(accB[id + 3] + b1)));
                    *(__half2*)(gpark + r0 * BP + off) = __floats2half2_rn(s0, s1);
                    *(__half2*)(gpark + r1 * BP + off) = __floats2half2_rn(s2, s3);
                }
            }
            zero_n(accB, 64);
        } else if (idx == 27) {
            store_act<8>(buf, accB, bias_sh + 896, mb, nb256, g, t);
            zero_n(accA, 32);
        } else if (idx == 31) {
            store_act<4>(buf, accA, bias_sh + 1152, mb, nb128, g, t);
            zero_n(accB, 64);
        } else if (idx == 35) {                            // combine + reduce
            #pragma unroll
            for (int nt = 0; nt < 8; nt++) {
                int c = nb256 + nt * 8 + 2 * t;
                int off = (c >> 4) * 32 + posu((c & 15) >> 1) * 2;
                float b0 = bias_sh[1280 + c], b1 = bias_sh[1280 + c + 1];
                float s0 = 0.f, s1 = 0.f;
                #pragma unroll
                for (int mt = 0; mt < 2; mt++) {
                    int id = (mt * 8 + nt) * 4;
                    int r0 = mb + mt * 16 + g, r1 = r0 + 8;
                    __half2 hg0 = *(__half2*)(gpark + r0 * BP + off);
                    __half2 hg1 = *(__half2*)(gpark + r1 * BP + off);
                    float m0 = mask_sh[r0], m1 = mask_sh[r1];
                    s0 += m0 * __low2float(hg0)  * (accB[id]     + b0)
                        + m1 * __low2float(hg1)  * (accB[id + 2] + b0);
                    s1 += m0 * __high2float(hg0) * (accB[id + 1] + b1)
                        + m1 * __high2float(hg1) * (accB[id + 3] + b1);
                }
                // reduce over the 32 rows this warp owns (g via xor 4/8/16)
                s0 += __shfl_xor_sync(0xffffffffu, s0, 4);
                s1 += __shfl_xor_sync(0xffffffffu, s1, 4);
                s0 += __shfl_xor_sync(0xffffffffu, s0, 8);
                s1 += __shfl_xor_sync(0xffffffffu, s1, 8);
                s0 += __shfl_xor_sync(0xffffffffu, s0, 16);
                s1 += __shfl_xor_sync(0xffffffffu, s1, 16);
                if (lane < 4) {
                    atomicAdd(&out[bidx * 256 + c],     s0);
                    atomicAdd(&out[bidx * 256 + c + 1], s1);
                }
            }
        }
    }
}

extern "C" void kernel_launch(void* const* d_in, const int* in_sizes, int n_in,
                              void* d_out, int out_size) {
    const float* h0  = (const float*)d_in[0];
    const float* hT  = (const float*)d_in[1];
    const float* gW0 = (const float*)d_in[2];  const float* gb0 = (const float*)d_in[3];
    const float* gW1 = (const float*)d_in[4];  const float* gb1 = (const float*)d_in[5];
    const float* gW2 = (const float*)d_in[6];  const float* gb2 = (const float*)d_in[7];
    const float* gW3 = (const float*)d_in[8];  const float* gb3 = (const float*)d_in[9];
    const float* oW0 = (const float*)d_in[10]; const float* ob0 = (const float*)d_in[11];
    const float* oW1 = (const float*)d_in[12]; const float* ob1 = (const float*)d_in[13];
    const float* oW2 = (const float*)d_in[14]; const float* ob2 = (const float*)d_in[15];
    const float* oW3 = (const float*)d_in[16]; const float* ob3 = (const float*)d_in[17];
    float* out = (float*)d_out;

    cudaFuncSetAttribute(readout_kernel,
                         cudaFuncAttributeMaxDynamicSharedMemorySize, SMEM_BYTES);
    cudaMemsetAsync(d_out, 0, (size_t)out_size * sizeof(float), 0);
    pack_kernel<<<NCHUNK, 256>>>(gW0, gW1, gW2, gW3, oW0, oW1, oW2, oW3);
    readout_kernel<<<2048, THREADS, SMEM_BYTES>>>(
        h0, hT, gb0, gb1, gb2, gb3, ob0, ob1, ob2, ob3, out);
}

// round 10
// speedup vs baseline: 3.3246x; 1.1019x over previous
#include <cuda_runtime.h>
#include <cuda_fp16.h>
#include <cstdint>

// ---------------------------------------------------------------------------
// Fused gated-readout v6 (fp16 m16n8k16 via ldmatrix.x4, 2 CTAs/SM):
//   gate = sigmoid(MLP_g([h0;hT]))   512->128->256->128->256
//   val  = MLP_o(hT)                 256->128->256->128->256
//   out[b,:] = sum_n mask(b,n) * gate(b,n,:) * val(b,n,:)
// One CTA = 64 rows, 8 warps (2M x 4N).  All fragment loads are ldmatrix.x4
// on 16B-XOR-swizzled k-contiguous tiles (bank-conflict-free).  Weights
// pre-packed into ldmatrix-native chunk images, streamed via cp.async through
// a 3-slot ring -> ONE __syncthreads per chunk.  Gate sigmoid parked in SMEM.
// ---------------------------------------------------------------------------

#define THREADS     256
#define NCHUNK      36
#define CHUNK_BYTES 16384
#define BP          512                 // A-buffer row pitch (bytes), swizzled

#define BUF_OFF     0                   // 64 x 512 = 32768
#define GP_OFF      32768               // park buffer, 64 x 512
#define SLOT_OFF    65536               // 3 x 16384 weight slots
#define MASK_OFF    114688              // 64 fp32
#define SMEM_BYTES  114944

__device__ __align__(16) unsigned short g_wpack[NCHUNK * 8192];

// A-operand k-unit offset of each chunk (16B units into the swizzled row)
__constant__ int c_u0[NCHUNK] = {0,8,16,24, 0,8,16,24, 0,8,16,24,
                                 0,4,8,12,  0,8,16,24, 0,4,8,12,
                                 0,4,8,12,  0,8,16,24, 0,4,8,12};

__device__ __forceinline__ void hmma(float* d,
                                     uint32_t a0, uint32_t a1, uint32_t a2, uint32_t a3,
                                     uint32_t b0, uint32_t b1) {
    asm volatile(
        "mma.sync.aligned.m16n8k16.row.col.f32.f16.f16.f32 "
        "{%0,%1,%2,%3}, {%4,%5,%6,%7}, {%8,%9}, {%0,%1,%2,%3};"
        : "+f"(d[0]), "+f"(d[1]), "+f"(d[2]), "+f"(d[3])
        : "r"(a0), "r"(a1), "r"(a2), "r"(a3), "r"(b0), "r"(b1));
}

#define LDSM4(r, a) asm volatile( \
    "ldmatrix.sync.aligned.m8n8.x4.shared.b16 {%0,%1,%2,%3}, [%4];" \
    : "=r"((r)[0]), "=r"((r)[1]), "=r"((r)[2]), "=r"((r)[3]) : "r"(a))

// ---------------------------------------------------------------------------
// pack: chunk image = groups of 8 n-rows: [group][k-unit][n&7][16B].
// 8 consecutive n rows of one k-unit are 16B apart -> ldmatrix conflict-free.
// ---------------------------------------------------------------------------
__global__ void pack_kernel(const float* __restrict__ gW0, const float* __restrict__ gW1,
                            const float* __restrict__ gW2, const float* __restrict__ gW3,
                            const float* __restrict__ oW0, const float* __restrict__ oW1,
                            const float* __restrict__ oW2, const float* __restrict__ oW3) {
    int c = blockIdx.x;
    const float* W; int Nl, ks;
    if (c < 8)       { W = gW0; Nl = 128; ks = c * 64; }
    else if (c < 12) { W = oW0; Nl = 128; ks = (c - 8) * 64; }
    else if (c < 16) { W = gW1; Nl = 256; ks = (c - 12) * 32; }
    else if (c < 20) { W = gW2; Nl = 128; ks = (c - 16) * 64; }
    else if (c < 24) { W = gW3; Nl = 256; ks = (c - 20) * 32; }
    else if (c < 28) { W = oW1; Nl = 256; ks = (c - 24) * 32; }
    else if (c < 32) { W = oW2; Nl = 128; ks = (c - 28) * 64; }
    else             { W = oW3; Nl = 256; ks = (c - 32) * 32; }
    const int GSH = (Nl == 128) ? 512 : 256;          // group stride in ushorts
    unsigned short* dst = g_wpack + (size_t)c * 8192;
    for (int i = threadIdx.x; i < 8192; i += blockDim.x) {
        int n, kl;
        if (Nl == 128) { n = i >> 6; kl = i & 63; }
        else           { n = i >> 5; kl = i & 31; }
        int di = (n >> 3) * GSH + (kl >> 3) * 64 + (n & 7) * 8 + (kl & 7);
        dst[di] = __half_as_ushort(__float2half_rn(W[(size_t)(ks + kl) * Nl + n]));
    }
}

// ---------------------------------------------------------------------------
__device__ __forceinline__ void prefetch(char* smdst, int idx, int tid) {
    const char* src = (const char*)g_wpack + (size_t)idx * CHUNK_BYTES;
    uint32_t sb = (uint32_t)__cvta_generic_to_shared(smdst);
    #pragma unroll
    for (int i = 0; i < 4; i++) {
        int o = (tid + i * 256) * 16;
        asm volatile("cp.async.cg.shared.global [%0], [%1], 16;" :: "r"(sb + o), "l"(src + o));
    }
    asm volatile("cp.async.commit_group;");
}

// acc[2mt x NT x 4] += A[warp 32-row slice] @ W[warp n-slice] over KB k16 blocks
template <int KB, int NT, int GS>
__device__ __forceinline__ void mma_chunk(uint32_t abase, int u0, uint32_t wbase,
                                          float* acc, int mb, int nb, int lane) {
    const int sx  = lane & 7;
    const int hi  = lane >> 4;              // A k-unit select
    const int kb2 = (lane >> 3) & 1;        // B k-unit select
    const int dn  = sx + ((lane & 16) >> 1);
    const uint32_t arow = abase + (uint32_t)((mb + (lane & 15)) * BP);
    const uint32_t bln  = wbase + (uint32_t)((dn >> 3) * GS + (dn & 7) * 16 + kb2 * 128
                                             + (nb >> 3) * GS);
    #pragma unroll
    for (int kb = 0; kb < KB; kb++) {
        const uint32_t aoff = (uint32_t)((((u0 + 2 * kb + hi) ^ sx)) << 4);
        uint32_t a0[4], a1[4];
        LDSM4(a0, arow + aoff);
        LDSM4(a1, arow + 16u * BP + aoff);
        #pragma unroll
        for (int j = 0; j < NT / 2; j++) {
            uint32_t b[4];
            LDSM4(b, bln + (uint32_t)(2 * j * GS + kb * 256));
            hmma(acc + (2 * j) * 4,            a0[0], a0[1], a0[2], a0[3], b[0], b[1]);
            hmma(acc + (2 * j + 1) * 4,        a0[0], a0[1], a0[2], a0[3], b[2], b[3]);
            hmma(acc + (NT + 2 * j) * 4,       a1[0], a1[1], a1[2], a1[3], b[0], b[1]);
            hmma(acc + (NT + 2 * j + 1) * 4,   a1[0], a1[1], a1[2], a1[3], b[2], b[3]);
        }
    }
}

// relu(acc + bias) -> swizzled fp16 A operand rows
template <int NT>
__device__ __forceinline__ void store_act(char* __restrict__ dst, const float* acc,
                                          const float* __restrict__ bias,
                                          int mb, int nb, int g, int t) {
    #pragma unroll
    for (int nt = 0; nt < NT; nt++) {
        int c = nb + nt * 8 + 2 * t;
        float b0 = __ldg(bias + c), b1 = __ldg(bias + c + 1);
        int u = c >> 3, wb = (c & 7) * 2;
        #pragma unroll
        for (int mt = 0; mt < 2; mt++) {
            int id = (mt * NT + nt) * 4;
            int r0 = mb + mt * 16 + g, r1 = r0 + 8;
            *(__half2*)(dst + r0 * BP + ((u ^ (r0 & 7)) << 4) + wb) =
                __floats2half2_rn(fmaxf(acc[id] + b0, 0.f), fmaxf(acc[id + 1] + b1, 0.f));
            *(__half2*)(dst + r1 * BP + ((u ^ (r1 & 7)) << 4) + wb) =
                __floats2half2_rn(fmaxf(acc[id + 2] + b0, 0.f), fmaxf(acc[id + 3] + b1, 0.f));
        }
    }
}

// fp32 global tile -> swizzled fp16 A buffer (+ optional mask)
__device__ __forceinline__ void stage_in(char* __restrict__ buf, const float* __restrict__ X,
                                         size_t row0, float* mask_sh, int tid, bool domask) {
    int r = tid >> 2, q = tid & 3, sx = r & 7;
    const float4* src = (const float4*)(X + (row0 + r) * 256);
    float s = 0.f;
    #pragma unroll
    for (int i = 0; i < 8; i++) {
        int u = q * 8 + i;
        float4 v0 = src[2 * u], v1 = src[2 * u + 1];
        if (domask) s += v0.x + v0.y + v0.z + v0.w + v1.x + v1.y + v1.z + v1.w;
        union { uint4 u4; __half2 h[4]; } pk;
        pk.h[0] = __floats2half2_rn(v0.x, v0.y);
        pk.h[1] = __floats2half2_rn(v0.z, v0.w);
        pk.h[2] = __floats2half2_rn(v1.x, v1.y);
        pk.h[3] = __floats2half2_rn(v1.z, v1.w);
        *(uint4*)(buf + r * BP + ((u ^ sx) << 4)) = pk.u4;
    }
    if (domask) {
        s += __shfl_xor_sync(0xffffffffu, s, 1);
        s += __shfl_xor_sync(0xffffffffu, s, 2);
        if (q == 0) mask_sh[r] = (s > 0.f) ? 1.f : 0.f;
    }
}

__device__ __forceinline__ void zero_n(float* a, int n) {
    #pragma unroll
    for (int i = 0; i < 64; i++) if (i < n) a[i] = 0.f;
}

__global__ void __launch_bounds__(THREADS, 2)
readout_kernel(const float* __restrict__ h0, const float* __restrict__ hT,
               const float* __restrict__ gb0, const float* __restrict__ gb1,
               const float* __restrict__ gb2, const float* __restrict__ gb3,
               const float* __restrict__ ob0, const float* __restrict__ ob1,
               const float* __restrict__ ob2, const float* __restrict__ ob3,
               float* __restrict__ out) {
    extern __shared__ __align__(16) char sm[];
    char*  buf     = sm + BUF_OFF;
    char*  gpark   = sm + GP_OFF;
    float* mask_sh = (float*)(sm + MASK_OFF);
    const uint32_t smb = (uint32_t)__cvta_generic_to_shared(sm);

    const int tid  = threadIdx.x;
    const int lane = tid & 31;
    const int w    = tid >> 5;
    const int wm   = w & 1, wn = w >> 1;          // 2 x 4 warp grid
    const int g    = lane >> 2, t = lane & 3;
    const int mb    = wm * 32;
    const int nb128 = wn * 32, nb256 = wn * 64;

    const size_t row0 = (size_t)blockIdx.x * 64;
    const int bidx = (int)(blockIdx.x >> 2);

    prefetch(sm + SLOT_OFF, 0, tid);
    prefetch(sm + SLOT_OFF + CHUNK_BYTES, 1, tid);
    stage_in(buf, h0, row0, mask_sh, tid, true);

    float accA[32], accV[32], accB[64];
    zero_n(accA, 32); zero_n(accV, 32);

    for (int idx = 0; idx < NCHUNK; idx++) {
        if (idx == NCHUNK - 1) asm volatile("cp.async.wait_group 0;");
        else                   asm volatile("cp.async.wait_group 1;");
        __syncthreads();
        // slot (idx-1)%3 freed by the barrier above -> prefetch overlaps mma
        if (idx + 2 < NCHUNK)
            prefetch(sm + SLOT_OFF + ((idx + 2) % 3) * CHUNK_BYTES, idx + 2, tid);

        const uint32_t ws = smb + SLOT_OFF + (uint32_t)((idx % 3) * CHUNK_BYTES);
        const int u0 = c_u0[idx];

        if (idx < 8)       mma_chunk<4,4,1024>(smb, u0, ws, accA, mb, nb128, lane);
        else if (idx < 12) mma_chunk<4,4,1024>(smb, u0, ws, accV, mb, nb128, lane);
        else if (idx < 16) mma_chunk<2,8,512> (smb, u0, ws, accB, mb, nb256, lane);
        else if (idx < 20) mma_chunk<4,4,1024>(smb, u0, ws, accA, mb, nb128, lane);
        else if (idx < 24) mma_chunk<2,8,512> (smb, u0, ws, accB, mb, nb256, lane);
        else if (idx < 28) mma_chunk<2,8,512> (smb, u0, ws, accB, mb, nb256, lane);
        else if (idx < 32) mma_chunk<4,4,1024>(smb, u0, ws, accA, mb, nb128, lane);
        else               mma_chunk<2,8,512> (smb, u0, ws, accB, mb, nb256, lane);

        if (idx == 3) {                                   // h0 -> hT restage
            __syncthreads();
            stage_in(buf, hT, row0, nullptr, tid, false);
        } else if (idx == 11) {                           // gate act -> buf, value act -> park
            __syncthreads();
            store_act<4>(buf,   accA, gb0, mb, nb128, g, t);
            store_act<4>(gpark, accV, ob0, mb, nb128, g, t);
            zero_n(accB, 64);
        } else if (idx == 15) {
            __syncthreads();
            store_act<8>(buf, accB, gb1, mb, nb256, g, t);
            zero_n(accA, 32);
        } else if (idx == 19) {
            __syncthreads();
            store_act<4>(buf, accA, gb2, mb, nb128, g, t);
            zero_n(accB, 64);
        } else if (idx == 23) {
            __syncthreads();
            // parked value act (units 0-15, swizzle-identical) -> buf
            #pragma unroll
            for (int j = 0; j < 4; j++) {
                int tt = tid + j * 256;
                int r = tt >> 4, off = (tt & 15) * 16;
                *(float4*)(buf + r * BP + off) = *(const float4*)(gpark + r * BP + off);
            }
            __syncthreads();
            // sigmoid(gate L3 + gb3) -> gpark (fp16, swizzled)
            #pragma unroll
            for (int nt = 0; nt < 8; nt++) {
                int c = nb256 + nt * 8 + 2 * t;
                float b0 = __ldg(gb3 + c), b1 = __ldg(gb3 + c + 1);
                int u = c >> 3, wb = (c & 7) * 2;
                #pragma unroll
                for (int mt = 0; mt < 2; mt++) {
                    int id = (mt * 8 + nt) * 4;
                    int r0 = mb + mt * 16 + g, r1 = r0 + 8;
                    float s0 = 1.f / (1.f + __expf(-(accB[id]     + b0)));
                    float s1 = 1.f / (1.f + __expf(-(accB[id + 1] + b1)));
                    float s2 = 1.f / (1.f + __expf(-(accB[id + 2] + b0)));
                    float s3 = 1.f / (1.f + __expf(-(accB[id + 3] + b1)));
                    *(__half2*)(gpark + r0 * BP + ((u ^ (r0 & 7)) << 4) + wb) =
                        __floats2half2_rn(s0, s1);
                    *(__half2*)(gpark + r1 * BP + ((u ^ (r1 & 7)) << 4) + wb) =
                        __floats2half2_rn(s2, s3);
                }
            }
            zero_n(accB, 64);
        } else if (idx == 27) {
            __syncthreads();
            store_act<8>(buf, accB, ob1, mb, nb256, g, t);
            zero_n(accA, 32);
        } else if (idx == 31) {
            __syncthreads();
            store_act<4>(buf, accA, ob2, mb, nb128, g, t);
            zero_n(accB, 64);
        } else if (idx == 35) {                           // combine + node reduction
            #pragma unroll
            for (int nt = 0; nt < 8; nt++) {
                int c = nb256 + nt * 8 + 2 * t;
                float b0 = __ldg(ob3 + c), b1 = __ldg(ob3 + c + 1);
                int u = c >> 3, wb = (c & 7) * 2;
                float s0 = 0.f, s1 = 0.f;
                #pragma unroll
                for (int mt = 0; mt < 2; mt++) {
                    int id = (mt * 8 + nt) * 4;
                    int r0 = mb + mt * 16 + g, r1 = r0 + 8;
                    __half2 hg0 = *(__half2*)(gpark + r0 * BP + ((u ^ (r0 & 7)) << 4) + wb);
                    __half2 hg1 = *(__half2*)(gpark + r1 * BP + ((u ^ (r1 & 7)) << 4) + wb);
                    float m0 = mask_sh[r0], m1 = mask_sh[r1];
                    s0 += m0 * __low2float(hg0)  * (accB[id]     + b0)
                        + m1 * __low2float(hg1)  * (accB[id + 2] + b0);
                    s1 += m0 * __high2float(hg0) * (accB[id + 1] + b1)
                        + m1 * __high2float(hg1) * (accB[id + 3] + b1);
                }
                s0 += __shfl_xor_sync(0xffffffffu, s0, 4);
                s1 += __shfl_xor_sync(0xffffffffu, s1, 4);
                s0 += __shfl_xor_sync(0xffffffffu, s0, 8);
                s1 += __shfl_xor_sync(0xffffffffu, s1, 8);
                s0 += __shfl_xor_sync(0xffffffffu, s0, 16);
                s1 += __shfl_xor_sync(0xffffffffu, s1, 16);
                if (lane < 4) {
                    atomicAdd(&out[bidx * 256 + c],     s0);
                    atomicAdd(&out[bidx * 256 + c + 1], s1);
                }
            }
        }
    }
}

extern "C" void kernel_launch(void* const* d_in, const int* in_sizes, int n_in,
                              void* d_out, int out_size) {
    const float* h0  = (const float*)d_in[0];
    const float* hT  = (const float*)d_in[1];
    const float* gW0 = (const float*)d_in[2];  const float* gb0 = (const float*)d_in[3];
    const float* gW1 = (const float*)d_in[4];  const float* gb1 = (const float*)d_in[5];
    const float* gW2 = (const float*)d_in[6];  const float* gb2 = (const float*)d_in[7];
    const float* gW3 = (const float*)d_in[8];  const float* gb3 = (const float*)d_in[9];
    const float* oW0 = (const float*)d_in[10]; const float* ob0 = (const float*)d_in[11];
    const float* oW1 = (const float*)d_in[12]; const float* ob1 = (const float*)d_in[13];
    const float* oW2 = (const float*)d_in[14]; const float* ob2 = (const float*)d_in[15];
    const float* oW3 = (const float*)d_in[16]; const float* ob3 = (const float*)d_in[17];
    float* out = (float*)d_out;

    cudaFuncSetAttribute(readout_kernel,
                         cudaFuncAttributeMaxDynamicSharedMemorySize, SMEM_BYTES);
    cudaMemsetAsync(d_out, 0, (size_t)out_size * sizeof(float), 0);
    pack_kernel<<<NCHUNK, 256>>>(gW0, gW1, gW2, gW3, oW0, oW1, oW2, oW3);
    readout_kernel<<<2048, THREADS, SMEM_BYTES>>>(
        h0, hT, gb0, gb1, gb2, gb3, ob0, ob1, ob2, ob3, out);
}